// round 12
// baseline (speedup 1.0000x reference)
#include <cuda_runtime.h>
#include <cuda_fp16.h>
#include <cstdint>

#define Tt 4
#define Nn 50000
#define Ee 800000
#define Dd 256
#define D4 64
#define NT (Tt * Nn)        // 200000
#define ET (Tt * Ee)        // 3200000
#define SCAN_BLK 49         // ceil(200000/4096)

// ---------------- scratch ----------------
__device__ __half g_h0[(size_t)Nn * Dd];
__device__ __half g_h1[(size_t)Nn * Dd];
__device__ __half g_h2[(size_t)Nn * Dd];
__device__ __half g_h3[(size_t)Nn * Dd];
__device__ __half g_x[(size_t)NT * Dd];      // X (fp16)
__device__ __half g_w[3][Dd * Dd];           // W^T (fp16) [N,K]
__device__ float g_dinv[NT];
__device__ int   g_cnt[NT];
__device__ int   g_cur[NT];
__device__ int   g_ptr[NT + 1];
__device__ int   g_bsum[64];
__device__ int   g_boff[64];
__device__ uint2 g_eprm[ET];                 // packed (row, norm) per edge

// ---------------- helpers ----------------
__device__ __forceinline__ void h8f(uint4 v, float* f) {
    float2 p;
    p = __half22float2(*reinterpret_cast<__half2*>(&v.x)); f[0] = p.x; f[1] = p.y;
    p = __half22float2(*reinterpret_cast<__half2*>(&v.y)); f[2] = p.x; f[3] = p.y;
    p = __half22float2(*reinterpret_cast<__half2*>(&v.z)); f[4] = p.x; f[5] = p.y;
    p = __half22float2(*reinterpret_cast<__half2*>(&v.w)); f[6] = p.x; f[7] = p.y;
}
__device__ __forceinline__ uint32_t f2h2(float a, float b) {
    __half2 t = __floats2half2_rn(a, b);
    return *reinterpret_cast<uint32_t*>(&t);
}

// ---------------- batched prep ----------------
__global__ void k_init(float* __restrict__ deg, int* __restrict__ cnt) {
    int i = blockIdx.x * blockDim.x + threadIdx.x;
    if (i < NT) { deg[i] = 1.0f; cnt[i] = 0; }
}

__global__ void k_edge_prep(const int* __restrict__ ei_all, const float* __restrict__ w_all,
                            float* __restrict__ deg, int* __restrict__ cnt) {
    int ge = blockIdx.x * blockDim.x + threadIdx.x;
    if (ge < ET) {
        int t = ge / Ee, e = ge - t * Ee;
        int c = ei_all[(size_t)t * 2 * Ee + Ee + e];
        int gc = t * Nn + c;
        atomicAdd(&deg[gc], w_all[ge]);
        atomicAdd(&cnt[gc], 1);
    }
}

// scan1 + finalize_dinv fused (prep-branch local)
__global__ void __launch_bounds__(1024)
k_scan1(const int* __restrict__ cnt, int* __restrict__ ptr, int* __restrict__ cur,
        int* __restrict__ bsum, float* __restrict__ deg) {
    __shared__ int wt[32];
    int tid = threadIdx.x, lane = tid & 31, wid = tid >> 5;
    int i0 = blockIdx.x * 4096 + tid * 4;
    int4 v = make_int4(0, 0, 0, 0);
    if (i0 + 3 < NT) v = *(const int4*)(cnt + i0);
    else {
        if (i0 < NT)     v.x = cnt[i0];
        if (i0 + 1 < NT) v.y = cnt[i0 + 1];
        if (i0 + 2 < NT) v.z = cnt[i0 + 2];
    }
#pragma unroll
    for (int k = 0; k < 4; k++) {
        int i = i0 + k;
        if (i < NT) {
            float d = deg[i];
            deg[i] = (d > 0.0f) ? rsqrtf(d) : 0.0f;
        }
    }
    int tsum = v.x + v.y + v.z + v.w;
    int s = tsum;
#pragma unroll
    for (int off = 1; off < 32; off <<= 1) {
        int t = __shfl_up_sync(0xffffffffu, s, off);
        if (lane >= off) s += t;
    }
    if (lane == 31) wt[wid] = s;
    __syncthreads();
    if (wid == 0) {
        int ws = wt[lane];
#pragma unroll
        for (int off = 1; off < 32; off <<= 1) {
            int t = __shfl_up_sync(0xffffffffu, ws, off);
            if (lane >= off) ws += t;
        }
        wt[lane] = ws;
    }
    __syncthreads();
    int excl = s - tsum + (wid > 0 ? wt[wid - 1] : 0);
    int p = excl;
    if (i0 < NT)     { cur[i0] = p;     ptr[i0 + 1] = p + v.x; } p += v.x;
    if (i0 + 1 < NT) { cur[i0 + 1] = p; ptr[i0 + 2] = p + v.y; } p += v.y;
    if (i0 + 2 < NT) { cur[i0 + 2] = p; ptr[i0 + 3] = p + v.z; } p += v.z;
    if (i0 + 3 < NT) { cur[i0 + 3] = p; ptr[i0 + 4] = p + v.w; }
    if (tid == 1023) bsum[blockIdx.x] = excl + tsum;
}

__global__ void k_scan2(const int* __restrict__ bsum, int* __restrict__ boff,
                        int* __restrict__ ptr) {
    if (threadIdx.x == 0) {
        ptr[0] = 0;
        int run = 0;
        for (int b = 0; b < SCAN_BLK; b++) { boff[b] = run; run += bsum[b]; }
    }
}

__global__ void __launch_bounds__(1024)
k_scan3(const int* __restrict__ boff, int* __restrict__ ptr, int* __restrict__ cur) {
    int off = boff[blockIdx.x];
    int i0 = blockIdx.x * 4096 + threadIdx.x * 4;
#pragma unroll
    for (int k = 0; k < 4; k++) {
        int i = i0 + k;
        if (i < NT) { cur[i] += off; ptr[i + 1] += off; }
    }
}

__global__ void k_permute(const int* __restrict__ ei_all, const float* __restrict__ w_all,
                          const float* __restrict__ dinv, int* __restrict__ cur,
                          uint2* __restrict__ eprm) {
    int ge = blockIdx.x * blockDim.x + threadIdx.x;
    if (ge < ET) {
        int t = ge / Ee, e = ge - t * Ee;
        const int* base = ei_all + (size_t)t * 2 * Ee;
        int r = base[e], c = base[Ee + e];
        int gr = t * Nn + r, gc = t * Nn + c;
        float nm = dinv[gr] * w_all[ge] * dinv[gc];
        int pos = atomicAdd(&cur[gc], 1);
        eprm[pos] = make_uint2((uint32_t)r, __float_as_uint(nm));
    }
}

__global__ void k_wprep_all(const float* __restrict__ W0, const float* __restrict__ W1,
                            const float* __restrict__ W2, __half* __restrict__ wt) {
    int idx = blockIdx.x * blockDim.x + threadIdx.x;
    if (idx < 3 * Dd * Dd) {
        int l = idx >> 16, r = idx & 65535;
        int n = r >> 8, k = r & 255;
        const float* W = (l == 0) ? W0 : (l == 1) ? W1 : W2;
        wt[idx] = __float2half_rn(W[k * Dd + n]);
    }
}

__global__ void k_gather(const int* __restrict__ ids, const float4* __restrict__ emb,
                         uint2* __restrict__ x) {
    int idx = blockIdx.x * blockDim.x + threadIdx.x;
    if (idx < NT * 64) {
        int i = idx >> 6, q = idx & 63;
        float4 v = emb[(size_t)ids[i] * 64 + q];
        x[idx] = make_uint2(f2h2(v.x, v.y), f2h2(v.z, v.w));
    }
}

// ---------------- mma.sync fp16 GEMM: 128x128x32, 256 threads (proven tile) --------
__device__ __forceinline__ uint32_t swz(int row, int c) {
    return (uint32_t)(row * 64 + ((c ^ ((row >> 1) & 3)) << 4));
}

#define GEMM_SMEM 32768

__global__ void __launch_bounds__(256)
k_gemm_mma(const __half* __restrict__ x, const __half* __restrict__ wt,
           __half* __restrict__ H) {
    extern __shared__ __align__(128) char sm[];

    const int tid = threadIdx.x;
    const int wid = tid >> 5, lane = tid & 31;
    const int m0 = blockIdx.x * 128, n0 = blockIdx.y * 128;
    const int mw = wid >> 2, nw = wid & 3;

    float acc[4][4][4] = {};

    auto issue = [&](int kc, int stage) {
        char* sbase = sm + stage * 16384;
#pragma unroll
        for (int i = 0; i < 4; i++) {
            int u = tid + i * 256;
            int tile = u >> 9, idx = u & 511;
            int row = idx >> 2, c = idx & 3;
            uint32_t dst = (uint32_t)__cvta_generic_to_shared(
                sbase + tile * 8192 + swz(row, c));
            if (tile == 0) {
                int gm = m0 + row;
                int ok = (gm < Nn);
                const void* src = x + (size_t)(ok ? gm : 0) * Dd + kc * 32 + c * 8;
                int sz = ok ? 16 : 0;
                asm volatile("cp.async.ca.shared.global [%0], [%1], 16, %2;"
                             :: "r"(dst), "l"(src), "r"(sz));
            } else {
                const void* src = wt + (size_t)(n0 + row) * Dd + kc * 32 + c * 8;
                asm volatile("cp.async.ca.shared.global [%0], [%1], 16;"
                             :: "r"(dst), "l"(src));
            }
        }
        asm volatile("cp.async.commit_group;");
    };

    issue(0, 0);
    for (int it = 0; it < 8; it++) {
        int buf = it & 1;
        if (it + 1 < 8) {
            issue(it + 1, buf ^ 1);
            asm volatile("cp.async.wait_group 1;");
        } else {
            asm volatile("cp.async.wait_group 0;");
        }
        __syncthreads();
        char* pA = sm + buf * 16384;
        char* pB = pA + 8192;

#pragma unroll
        for (int ks = 0; ks < 2; ks++) {
            int ac = ks * 2 + ((lane >> 4) & 1);
            int brow = (lane & 7) + ((lane & 16) ? 8 : 0);
            int bc = ks * 2 + ((lane & 8) ? 1 : 0);
            uint32_t af[4][4];
#pragma unroll
            for (int mt = 0; mt < 4; mt++) {
                int row = mw * 64 + mt * 16 + (lane & 15);
                uint32_t a = (uint32_t)__cvta_generic_to_shared(pA + swz(row, ac));
                asm volatile("ldmatrix.sync.aligned.m8n8.x4.shared.b16 {%0,%1,%2,%3}, [%4];"
                             : "=r"(af[mt][0]), "=r"(af[mt][1]),
                               "=r"(af[mt][2]), "=r"(af[mt][3]) : "r"(a));
            }
            uint32_t bf[4][2];
#pragma unroll
            for (int ntp = 0; ntp < 2; ntp++) {
                int row = nw * 32 + ntp * 16 + brow;
                uint32_t b = (uint32_t)__cvta_generic_to_shared(pB + swz(row, bc));
                uint32_t r0, r1, r2, r3;
                asm volatile("ldmatrix.sync.aligned.m8n8.x4.shared.b16 {%0,%1,%2,%3}, [%4];"
                             : "=r"(r0), "=r"(r1), "=r"(r2), "=r"(r3) : "r"(b));
                bf[ntp * 2][0] = r0; bf[ntp * 2][1] = r1;
                bf[ntp * 2 + 1][0] = r2; bf[ntp * 2 + 1][1] = r3;
            }
#pragma unroll
            for (int mt = 0; mt < 4; mt++)
#pragma unroll
                for (int nt = 0; nt < 4; nt++) {
                    asm volatile(
                        "mma.sync.aligned.m16n8k16.row.col.f32.f16.f16.f32 "
                        "{%0,%1,%2,%3}, {%4,%5,%6,%7}, {%8,%9}, {%0,%1,%2,%3};"
                        : "+f"(acc[mt][nt][0]), "+f"(acc[mt][nt][1]),
                          "+f"(acc[mt][nt][2]), "+f"(acc[mt][nt][3])
                        : "r"(af[mt][0]), "r"(af[mt][1]), "r"(af[mt][2]), "r"(af[mt][3]),
                          "r"(bf[nt][0]), "r"(bf[nt][1]));
                }
        }
        __syncthreads();
    }

#pragma unroll
    for (int mt = 0; mt < 4; mt++) {
        int mm = m0 + mw * 64 + mt * 16 + (lane >> 2);
#pragma unroll
        for (int nt = 0; nt < 4; nt++) {
            int cc = n0 + nw * 32 + nt * 8 + 2 * (lane & 3);
            if (mm < Nn)
                *(uint32_t*)(H + (size_t)mm * Dd + cc) = f2h2(acc[mt][nt][0], acc[mt][nt][1]);
            if (mm + 8 < Nn)
                *(uint32_t*)(H + (size_t)(mm + 8) * Dd + cc) = f2h2(acc[mt][nt][2], acc[mt][nt][3]);
        }
    }
}

// ---------------- aggregate: warp/node, 2x edge unroll (proven), packed edges ------
__global__ void __launch_bounds__(256)
k_aggregate(const int* __restrict__ ptr, const uint2* __restrict__ eprm,
            const uint4* __restrict__ H,
            const float* __restrict__ dinv, const float4* __restrict__ bias,
            float4* __restrict__ outF, uint4* __restrict__ ox) {
    int warp = (blockIdx.x * blockDim.x + threadIdx.x) >> 5;
    int lane = threadIdx.x & 31;
    if (warp >= Nn) return;
    int node = warp;

    float s = dinv[node];
    s = s * s;
    float f[8], acc[8];
    h8f(H[(size_t)node * 32 + lane], f);
    float4 b0 = bias[lane * 2], b1 = bias[lane * 2 + 1];
    acc[0] = fmaf(s, f[0], b0.x); acc[1] = fmaf(s, f[1], b0.y);
    acc[2] = fmaf(s, f[2], b0.z); acc[3] = fmaf(s, f[3], b0.w);
    acc[4] = fmaf(s, f[4], b1.x); acc[5] = fmaf(s, f[5], b1.y);
    acc[6] = fmaf(s, f[6], b1.z); acc[7] = fmaf(s, f[7], b1.w);

    int jb = ptr[node], je = ptr[node + 1];
    int j = jb;
    for (; j + 1 < je; j += 2) {
        uint2 ea = eprm[j], eb = eprm[j + 1];
        float na = __uint_as_float(ea.y), nb = __uint_as_float(eb.y);
        uint4 va = H[(size_t)ea.x * 32 + lane];
        uint4 vb = H[(size_t)eb.x * 32 + lane];
        float fa[8], fb[8];
        h8f(va, fa); h8f(vb, fb);
#pragma unroll
        for (int i = 0; i < 8; i++) acc[i] = fmaf(na, fa[i], acc[i]);
#pragma unroll
        for (int i = 0; i < 8; i++) acc[i] = fmaf(nb, fb[i], acc[i]);
    }
    if (j < je) {
        uint2 er = eprm[j];
        float nm = __uint_as_float(er.y);
        float fr[8];
        h8f(H[(size_t)er.x * 32 + lane], fr);
#pragma unroll
        for (int i = 0; i < 8; i++) acc[i] = fmaf(nm, fr[i], acc[i]);
    }

    if (outF) {
        float4* op = outF + (size_t)node * D4 + lane * 2;
        op[0] = make_float4(acc[0], acc[1], acc[2], acc[3]);
        op[1] = make_float4(acc[4], acc[5], acc[6], acc[7]);
    }
    if (ox) {
        ox[(size_t)node * 32 + lane] = make_uint4(f2h2(acc[0], acc[1]), f2h2(acc[2], acc[3]),
                                                  f2h2(acc[4], acc[5]), f2h2(acc[6], acc[7]));
    }
}

// ---------------- launch (round-8 proven topology) ----------------
extern "C" void kernel_launch(void* const* d_in, const int* in_sizes, int n_in,
                              void* d_out, int out_size) {
    const int*   ids_all = (const int*)d_in[0];
    const int*   ei_all  = (const int*)d_in[1];
    const float* w_all   = (const float*)d_in[2];
    const float* emb     = (const float*)d_in[3];
    const float* Ws[3] = {(const float*)d_in[4], (const float*)d_in[6], (const float*)d_in[8]};
    const float* bs[3] = {(const float*)d_in[5], (const float*)d_in[7], (const float*)d_in[9]};
    float* out = (float*)d_out;

    void *ph0, *ph1, *ph2, *ph3, *px, *pw, *pd, *pc, *pu, *pp, *pe, *pbs, *pbo;
    cudaGetSymbolAddress(&ph0, g_h0);
    cudaGetSymbolAddress(&ph1, g_h1);
    cudaGetSymbolAddress(&ph2, g_h2);
    cudaGetSymbolAddress(&ph3, g_h3);
    cudaGetSymbolAddress(&px,  g_x);
    cudaGetSymbolAddress(&pw,  g_w);
    cudaGetSymbolAddress(&pd,  g_dinv);
    cudaGetSymbolAddress(&pc,  g_cnt);
    cudaGetSymbolAddress(&pu,  g_cur);
    cudaGetSymbolAddress(&pp,  g_ptr);
    cudaGetSymbolAddress(&pe,  g_eprm);
    cudaGetSymbolAddress(&pbs, g_bsum);
    cudaGetSymbolAddress(&pbo, g_boff);
    __half* H[4] = {(__half*)ph0, (__half*)ph1, (__half*)ph2, (__half*)ph3};
    __half* x  = (__half*)px;
    __half* wt = (__half*)pw;
    float* dinv = (float*)pd;
    int* cnt = (int*)pc;
    int* cur = (int*)pu;
    int* ptr = (int*)pp;
    uint2* eprm = (uint2*)pe;
    int* bsum = (int*)pbs;
    int* boff = (int*)pbo;

    const int TPB = 256;
    static cudaStream_t st[4] = {nullptr, nullptr, nullptr, nullptr};
    static cudaEvent_t evStart = nullptr, evPrepG = nullptr;
    static cudaEvent_t evFork = nullptr, evJoin[4] = {nullptr, nullptr, nullptr, nullptr};
    if (!st[1]) {
        st[0] = (cudaStream_t)0;
        for (int i = 1; i < 4; i++) cudaStreamCreateWithFlags(&st[i], cudaStreamNonBlocking);
        cudaEventCreateWithFlags(&evStart, cudaEventDisableTiming);
        cudaEventCreateWithFlags(&evPrepG, cudaEventDisableTiming);
        cudaEventCreateWithFlags(&evFork, cudaEventDisableTiming);
        for (int i = 1; i < 4; i++) cudaEventCreateWithFlags(&evJoin[i], cudaEventDisableTiming);
        cudaFuncSetAttribute(k_gemm_mma, cudaFuncAttributeMaxDynamicSharedMemorySize,
                             GEMM_SMEM);
    }

    // ---- prep: two parallel branches (round-8 pattern) ----
    cudaEventRecord(evStart, st[0]);
    cudaStreamWaitEvent(st[1], evStart, 0);

    // branch A (st[1]): weights + gather
    k_wprep_all<<<(3 * Dd * Dd + TPB - 1) / TPB, TPB, 0, st[1]>>>(Ws[0], Ws[1], Ws[2], wt);
    k_gather<<<(NT * 64 + TPB - 1) / TPB, TPB, 0, st[1]>>>(ids_all, (const float4*)emb,
                                                           (uint2*)x);
    cudaEventRecord(evPrepG, st[1]);

    // branch B (st[0]): edge chain
    k_init<<<(NT + TPB - 1) / TPB, TPB, 0, st[0]>>>(dinv, cnt);
    k_edge_prep<<<(ET + TPB - 1) / TPB, TPB, 0, st[0]>>>(ei_all, w_all, dinv, cnt);
    k_scan1<<<SCAN_BLK, 1024, 0, st[0]>>>(cnt, ptr, cur, bsum, dinv);
    k_scan2<<<1, 32, 0, st[0]>>>(bsum, boff, ptr);
    k_scan3<<<SCAN_BLK, 1024, 0, st[0]>>>(boff, ptr, cur);
    k_permute<<<(ET + TPB - 1) / TPB, TPB, 0, st[0]>>>(ei_all, w_all, dinv, cur, eprm);

    // join branches, fork 4 timestep chains
    cudaStreamWaitEvent(st[0], evPrepG, 0);
    cudaEventRecord(evFork, st[0]);
    for (int i = 1; i < 4; i++) cudaStreamWaitEvent(st[i], evFork, 0);

    dim3 ggrid((Nn + 127) / 128, Dd / 128);
    int aggBlocks = (Nn * 32 + TPB - 1) / TPB;

    for (int t = 0; t < Tt; t++) {
        cudaStream_t s = st[t];
        __half* Hh = H[t];
        size_t xoff = (size_t)t * Nn * Dd;
        float* outT = out + xoff;

        for (int l = 0; l < 3; l++) {
            k_gemm_mma<<<ggrid, 256, GEMM_SMEM, s>>>(x + xoff,
                                                     wt + (size_t)l * Dd * Dd, Hh);
            bool last = (l == 2);
            k_aggregate<<<aggBlocks, TPB, 0, s>>>(ptr + (size_t)t * Nn, eprm,
                                                  (const uint4*)Hh, dinv + (size_t)t * Nn,
                                                  (const float4*)bs[l],
                                                  last ? (float4*)outT : (float4*)nullptr,
                                                  last ? (uint4*)nullptr
                                                       : (uint4*)(x + xoff));
        }
    }

    // join all
    for (int i = 1; i < 4; i++) {
        cudaEventRecord(evJoin[i], st[i]);
        cudaStreamWaitEvent(st[0], evJoin[i], 0);
    }
}

// round 13
// speedup vs baseline: 1.0678x; 1.0678x over previous
#include <cuda_runtime.h>
#include <cuda_fp16.h>
#include <cstdint>

#define Tt 4
#define Nn 50000
#define Ee 800000
#define Dd 256
#define D4 64
#define NT (Tt * Nn)        // 200000
#define ET (Tt * Ee)        // 3200000
#define SCAN_BLK 49         // ceil(200000/4096)

// ---------------- scratch ----------------
__device__ __half g_h0[(size_t)Nn * Dd];
__device__ __half g_h1[(size_t)Nn * Dd];
__device__ __half g_h2[(size_t)Nn * Dd];
__device__ __half g_h3[(size_t)Nn * Dd];
__device__ __half g_x[(size_t)NT * Dd];      // X (fp16)
__device__ __half g_w[3][Dd * Dd];           // W^T (fp16) [N,K]
__device__ float g_dinv[NT];
__device__ int   g_cnt[NT];
__device__ int   g_cur[NT];
__device__ int   g_ptr[NT + 1];
__device__ int   g_bsum[64];
__device__ int   g_boff[64];
__device__ int   g_erow[ET];
__device__ float g_enorm[ET];

// ---------------- helpers ----------------
__device__ __forceinline__ void h8f(uint4 v, float* f) {
    float2 p;
    p = __half22float2(*reinterpret_cast<__half2*>(&v.x)); f[0] = p.x; f[1] = p.y;
    p = __half22float2(*reinterpret_cast<__half2*>(&v.y)); f[2] = p.x; f[3] = p.y;
    p = __half22float2(*reinterpret_cast<__half2*>(&v.z)); f[4] = p.x; f[5] = p.y;
    p = __half22float2(*reinterpret_cast<__half2*>(&v.w)); f[6] = p.x; f[7] = p.y;
}
__device__ __forceinline__ uint32_t f2h2(float a, float b) {
    __half2 t = __floats2half2_rn(a, b);
    return *reinterpret_cast<uint32_t*>(&t);
}

// ---------------- batched prep ----------------
__global__ void k_init(float* __restrict__ deg, int* __restrict__ cnt) {
    int i = blockIdx.x * blockDim.x + threadIdx.x;
    if (i < NT) { deg[i] = 1.0f; cnt[i] = 0; }
}

__global__ void k_edge_prep(const int* __restrict__ ei_all, const float* __restrict__ w_all,
                            float* __restrict__ deg, int* __restrict__ cnt) {
    int ge = blockIdx.x * blockDim.x + threadIdx.x;
    if (ge < ET) {
        int t = ge / Ee, e = ge - t * Ee;
        int c = ei_all[(size_t)t * 2 * Ee + Ee + e];
        int gc = t * Nn + c;
        atomicAdd(&deg[gc], w_all[ge]);
        atomicAdd(&cnt[gc], 1);
    }
}

__global__ void k_finalize_dinv(float* __restrict__ deg) {
    int i = blockIdx.x * blockDim.x + threadIdx.x;
    if (i < NT) {
        float d = deg[i];
        deg[i] = (d > 0.0f) ? rsqrtf(d) : 0.0f;
    }
}

__global__ void __launch_bounds__(1024)
k_scan1(const int* __restrict__ cnt, int* __restrict__ ptr, int* __restrict__ cur,
        int* __restrict__ bsum) {
    __shared__ int wt[32];
    int tid = threadIdx.x, lane = tid & 31, wid = tid >> 5;
    int i0 = blockIdx.x * 4096 + tid * 4;
    int4 v = make_int4(0, 0, 0, 0);
    if (i0 + 3 < NT) v = *(const int4*)(cnt + i0);
    else {
        if (i0 < NT)     v.x = cnt[i0];
        if (i0 + 1 < NT) v.y = cnt[i0 + 1];
        if (i0 + 2 < NT) v.z = cnt[i0 + 2];
    }
    int tsum = v.x + v.y + v.z + v.w;
    int s = tsum;
#pragma unroll
    for (int off = 1; off < 32; off <<= 1) {
        int t = __shfl_up_sync(0xffffffffu, s, off);
        if (lane >= off) s += t;
    }
    if (lane == 31) wt[wid] = s;
    __syncthreads();
    if (wid == 0) {
        int ws = wt[lane];
#pragma unroll
        for (int off = 1; off < 32; off <<= 1) {
            int t = __shfl_up_sync(0xffffffffu, ws, off);
            if (lane >= off) ws += t;
        }
        wt[lane] = ws;
    }
    __syncthreads();
    int excl = s - tsum + (wid > 0 ? wt[wid - 1] : 0);
    int p = excl;
    if (i0 < NT)     { cur[i0] = p;     ptr[i0 + 1] = p + v.x; } p += v.x;
    if (i0 + 1 < NT) { cur[i0 + 1] = p; ptr[i0 + 2] = p + v.y; } p += v.y;
    if (i0 + 2 < NT) { cur[i0 + 2] = p; ptr[i0 + 3] = p + v.z; } p += v.z;
    if (i0 + 3 < NT) { cur[i0 + 3] = p; ptr[i0 + 4] = p + v.w; }
    if (tid == 1023) bsum[blockIdx.x] = excl + tsum;
}

__global__ void k_scan2(const int* __restrict__ bsum, int* __restrict__ boff,
                        int* __restrict__ ptr) {
    if (threadIdx.x == 0) {
        ptr[0] = 0;
        int run = 0;
        for (int b = 0; b < SCAN_BLK; b++) { boff[b] = run; run += bsum[b]; }
    }
}

__global__ void __launch_bounds__(1024)
k_scan3(const int* __restrict__ boff, int* __restrict__ ptr, int* __restrict__ cur) {
    int off = boff[blockIdx.x];
    int i0 = blockIdx.x * 4096 + threadIdx.x * 4;
#pragma unroll
    for (int k = 0; k < 4; k++) {
        int i = i0 + k;
        if (i < NT) { cur[i] += off; ptr[i + 1] += off; }
    }
}

__global__ void k_permute(const int* __restrict__ ei_all, const float* __restrict__ w_all,
                          const float* __restrict__ dinv, int* __restrict__ cur,
                          int* __restrict__ erow, float* __restrict__ enorm) {
    int ge = blockIdx.x * blockDim.x + threadIdx.x;
    if (ge < ET) {
        int t = ge / Ee, e = ge - t * Ee;
        const int* base = ei_all + (size_t)t * 2 * Ee;
        int r = base[e], c = base[Ee + e];
        int gr = t * Nn + r, gc = t * Nn + c;
        float nm = dinv[gr] * w_all[ge] * dinv[gc];
        int pos = atomicAdd(&cur[gc], 1);
        erow[pos] = r;
        enorm[pos] = nm;
    }
}

// W^T fp16: w[n*256+k] = fp16(W[k*256+n])
__global__ void k_wprep(const float* __restrict__ W, __half* __restrict__ wt) {
    int idx = blockIdx.x * blockDim.x + threadIdx.x;
    if (idx < Dd * Dd) {
        int n = idx >> 8, k = idx & 255;
        wt[idx] = __float2half_rn(W[k * Dd + n]);
    }
}

// embedding gather -> fp16 x
__global__ void k_gather(const int* __restrict__ ids, const float4* __restrict__ emb,
                         uint2* __restrict__ x) {
    int idx = blockIdx.x * blockDim.x + threadIdx.x;
    if (idx < NT * 64) {
        int i = idx >> 6, q = idx & 63;
        float4 v = emb[(size_t)ids[i] * 64 + q];
        x[idx] = make_uint2(f2h2(v.x, v.y), f2h2(v.z, v.w));
    }
}

// ---------------- mma.sync fp16 GEMM ----------------
__device__ __forceinline__ uint32_t swz(int row, int c) {
    return (uint32_t)(row * 64 + ((c ^ ((row >> 1) & 3)) << 4));
}

#define GEMM_SMEM 32768

__global__ void __launch_bounds__(256)
k_gemm_mma(const __half* __restrict__ x, const __half* __restrict__ wt,
           __half* __restrict__ H) {
    extern __shared__ __align__(128) char sm[];

    const int tid = threadIdx.x;
    const int wid = tid >> 5, lane = tid & 31;
    const int m0 = blockIdx.x * 128, n0 = blockIdx.y * 128;
    const int mw = wid >> 2, nw = wid & 3;

    float acc[4][4][4] = {};

    auto issue = [&](int kc, int stage) {
        char* sbase = sm + stage * 16384;
#pragma unroll
        for (int i = 0; i < 4; i++) {
            int u = tid + i * 256;
            int tile = u >> 9, idx = u & 511;
            int row = idx >> 2, c = idx & 3;
            uint32_t dst = (uint32_t)__cvta_generic_to_shared(
                sbase + tile * 8192 + swz(row, c));
            if (tile == 0) {
                int gm = m0 + row;
                int ok = (gm < Nn);
                const void* src = x + (size_t)(ok ? gm : 0) * Dd + kc * 32 + c * 8;
                int sz = ok ? 16 : 0;
                asm volatile("cp.async.ca.shared.global [%0], [%1], 16, %2;"
                             :: "r"(dst), "l"(src), "r"(sz));
            } else {
                const void* src = wt + (size_t)(n0 + row) * Dd + kc * 32 + c * 8;
                asm volatile("cp.async.ca.shared.global [%0], [%1], 16;"
                             :: "r"(dst), "l"(src));
            }
        }
        asm volatile("cp.async.commit_group;");
    };

    issue(0, 0);
    for (int it = 0; it < 8; it++) {
        int buf = it & 1;
        if (it + 1 < 8) {
            issue(it + 1, buf ^ 1);
            asm volatile("cp.async.wait_group 1;");
        } else {
            asm volatile("cp.async.wait_group 0;");
        }
        __syncthreads();
        char* pA = sm + buf * 16384;
        char* pB = pA + 8192;

#pragma unroll
        for (int ks = 0; ks < 2; ks++) {
            int ac = ks * 2 + ((lane >> 4) & 1);
            int brow = (lane & 7) + ((lane & 16) ? 8 : 0);
            int bc = ks * 2 + ((lane & 8) ? 1 : 0);
            uint32_t af[4][4];
#pragma unroll
            for (int mt = 0; mt < 4; mt++) {
                int row = mw * 64 + mt * 16 + (lane & 15);
                uint32_t a = (uint32_t)__cvta_generic_to_shared(pA + swz(row, ac));
                asm volatile("ldmatrix.sync.aligned.m8n8.x4.shared.b16 {%0,%1,%2,%3}, [%4];"
                             : "=r"(af[mt][0]), "=r"(af[mt][1]),
                               "=r"(af[mt][2]), "=r"(af[mt][3]) : "r"(a));
            }
            uint32_t bf[4][2];
#pragma unroll
            for (int ntp = 0; ntp < 2; ntp++) {
                int row = nw * 32 + ntp * 16 + brow;
                uint32_t b = (uint32_t)__cvta_generic_to_shared(pB + swz(row, bc));
                uint32_t r0, r1, r2, r3;
                asm volatile("ldmatrix.sync.aligned.m8n8.x4.shared.b16 {%0,%1,%2,%3}, [%4];"
                             : "=r"(r0), "=r"(r1), "=r"(r2), "=r"(r3) : "r"(b));
                bf[ntp * 2][0] = r0; bf[ntp * 2][1] = r1;
                bf[ntp * 2 + 1][0] = r2; bf[ntp * 2 + 1][1] = r3;
            }
#pragma unroll
            for (int mt = 0; mt < 4; mt++)
#pragma unroll
                for (int nt = 0; nt < 4; nt++) {
                    asm volatile(
                        "mma.sync.aligned.m16n8k16.row.col.f32.f16.f16.f32 "
                        "{%0,%1,%2,%3}, {%4,%5,%6,%7}, {%8,%9}, {%0,%1,%2,%3};"
                        : "+f"(acc[mt][nt][0]), "+f"(acc[mt][nt][1]),
                          "+f"(acc[mt][nt][2]), "+f"(acc[mt][nt][3])
                        : "r"(af[mt][0]), "r"(af[mt][1]), "r"(af[mt][2]), "r"(af[mt][3]),
                          "r"(bf[nt][0]), "r"(bf[nt][1]));
                }
        }
        __syncthreads();
    }

#pragma unroll
    for (int mt = 0; mt < 4; mt++) {
        int mm = m0 + mw * 64 + mt * 16 + (lane >> 2);
#pragma unroll
        for (int nt = 0; nt < 4; nt++) {
            int cc = n0 + nw * 32 + nt * 8 + 2 * (lane & 3);
            if (mm < Nn)
                *(uint32_t*)(H + (size_t)mm * Dd + cc) = f2h2(acc[mt][nt][0], acc[mt][nt][1]);
            if (mm + 8 < Nn)
                *(uint32_t*)(H + (size_t)(mm + 8) * Dd + cc) = f2h2(acc[mt][nt][2], acc[mt][nt][3]);
        }
    }
}

// ---------------- aggregate ----------------
__global__ void __launch_bounds__(256)
k_aggregate(const int* __restrict__ ptr, const int* __restrict__ erow,
            const float* __restrict__ enorm, const uint4* __restrict__ H,
            const float* __restrict__ dinv, const float4* __restrict__ bias,
            float4* __restrict__ outF, uint4* __restrict__ ox) {
    int warp = (blockIdx.x * blockDim.x + threadIdx.x) >> 5;
    int lane = threadIdx.x & 31;
    if (warp >= Nn) return;
    int node = warp;

    float s = dinv[node];
    s = s * s;
    float f[8], acc[8];
    h8f(H[(size_t)node * 32 + lane], f);
    float4 b0 = bias[lane * 2], b1 = bias[lane * 2 + 1];
    acc[0] = fmaf(s, f[0], b0.x); acc[1] = fmaf(s, f[1], b0.y);
    acc[2] = fmaf(s, f[2], b0.z); acc[3] = fmaf(s, f[3], b0.w);
    acc[4] = fmaf(s, f[4], b1.x); acc[5] = fmaf(s, f[5], b1.y);
    acc[6] = fmaf(s, f[6], b1.z); acc[7] = fmaf(s, f[7], b1.w);

    int jb = ptr[node], je = ptr[node + 1];
    int j = jb;
    for (; j + 1 < je; j += 2) {
        int ra = erow[j], rb = erow[j + 1];
        float na = enorm[j], nb = enorm[j + 1];
        uint4 va = H[(size_t)ra * 32 + lane];
        uint4 vb = H[(size_t)rb * 32 + lane];
        float fa[8], fb[8];
        h8f(va, fa); h8f(vb, fb);
#pragma unroll
        for (int i = 0; i < 8; i++) acc[i] = fmaf(na, fa[i], acc[i]);
#pragma unroll
        for (int i = 0; i < 8; i++) acc[i] = fmaf(nb, fb[i], acc[i]);
    }
    if (j < je) {
        int r = erow[j];
        float nm = enorm[j];
        float fr[8];
        h8f(H[(size_t)r * 32 + lane], fr);
#pragma unroll
        for (int i = 0; i < 8; i++) acc[i] = fmaf(nm, fr[i], acc[i]);
    }

    if (outF) {
        float4* op = outF + (size_t)node * D4 + lane * 2;
        op[0] = make_float4(acc[0], acc[1], acc[2], acc[3]);
        op[1] = make_float4(acc[4], acc[5], acc[6], acc[7]);
    }
    if (ox) {
        ox[(size_t)node * 32 + lane] = make_uint4(f2h2(acc[0], acc[1]), f2h2(acc[2], acc[3]),
                                                  f2h2(acc[4], acc[5]), f2h2(acc[6], acc[7]));
    }
}

// ---------------- launch ----------------
extern "C" void kernel_launch(void* const* d_in, const int* in_sizes, int n_in,
                              void* d_out, int out_size) {
    const int*   ids_all = (const int*)d_in[0];
    const int*   ei_all  = (const int*)d_in[1];
    const float* w_all   = (const float*)d_in[2];
    const float* emb     = (const float*)d_in[3];
    const float* Ws[3] = {(const float*)d_in[4], (const float*)d_in[6], (const float*)d_in[8]};
    const float* bs[3] = {(const float*)d_in[5], (const float*)d_in[7], (const float*)d_in[9]};
    float* out = (float*)d_out;

    void *ph0, *ph1, *ph2, *ph3, *px, *pw, *pd, *pc, *pu, *pp, *pe, *pm, *pbs, *pbo;
    cudaGetSymbolAddress(&ph0, g_h0);
    cudaGetSymbolAddress(&ph1, g_h1);
    cudaGetSymbolAddress(&ph2, g_h2);
    cudaGetSymbolAddress(&ph3, g_h3);
    cudaGetSymbolAddress(&px,  g_x);
    cudaGetSymbolAddress(&pw,  g_w);
    cudaGetSymbolAddress(&pd,  g_dinv);
    cudaGetSymbolAddress(&pc,  g_cnt);
    cudaGetSymbolAddress(&pu,  g_cur);
    cudaGetSymbolAddress(&pp,  g_ptr);
    cudaGetSymbolAddress(&pe,  g_erow);
    cudaGetSymbolAddress(&pm,  g_enorm);
    cudaGetSymbolAddress(&pbs, g_bsum);
    cudaGetSymbolAddress(&pbo, g_boff);
    __half* H[4] = {(__half*)ph0, (__half*)ph1, (__half*)ph2, (__half*)ph3};
    __half* x  = (__half*)px;
    __half* wt = (__half*)pw;
    float* dinv = (float*)pd;
    int* cnt = (int*)pc;
    int* cur = (int*)pu;
    int* ptr = (int*)pp;
    int* erow = (int*)pe;
    float* enrm = (float*)pm;
    int* bsum = (int*)pbs;
    int* boff = (int*)pbo;

    const int TPB = 256;
    static cudaStream_t st[4] = {nullptr, nullptr, nullptr, nullptr};
    static cudaEvent_t evStart = nullptr, evPrepG = nullptr, evPrepE = nullptr;
    static cudaEvent_t evFork = nullptr, evJoin[4] = {nullptr, nullptr, nullptr, nullptr};
    if (!st[1]) {
        st[0] = (cudaStream_t)0;
        for (int i = 1; i < 4; i++) cudaStreamCreateWithFlags(&st[i], cudaStreamNonBlocking);
        cudaEventCreateWithFlags(&evStart, cudaEventDisableTiming);
        cudaEventCreateWithFlags(&evPrepG, cudaEventDisableTiming);
        cudaEventCreateWithFlags(&evPrepE, cudaEventDisableTiming);
        cudaEventCreateWithFlags(&evFork, cudaEventDisableTiming);
        for (int i = 1; i < 4; i++) cudaEventCreateWithFlags(&evJoin[i], cudaEventDisableTiming);
        cudaFuncSetAttribute(k_gemm_mma, cudaFuncAttributeMaxDynamicSharedMemorySize,
                             GEMM_SMEM);
    }

    // ---- prep: two parallel branches ----
    cudaEventRecord(evStart, st[0]);
    cudaStreamWaitEvent(st[1], evStart, 0);

    // branch A (st[1]): weights + gather
    for (int l = 0; l < 3; l++)
        k_wprep<<<(Dd * Dd + TPB - 1) / TPB, TPB, 0, st[1]>>>(Ws[l],
                                                              wt + (size_t)l * Dd * Dd);
    k_gather<<<(NT * 64 + TPB - 1) / TPB, TPB, 0, st[1]>>>(ids_all, (const float4*)emb,
                                                           (uint2*)x);
    cudaEventRecord(evPrepG, st[1]);

    // branch B (st[0]): edge chain
    k_init<<<(NT + TPB - 1) / TPB, TPB, 0, st[0]>>>(dinv, cnt);
    k_edge_prep<<<(ET + TPB - 1) / TPB, TPB, 0, st[0]>>>(ei_all, w_all, dinv, cnt);
    k_finalize_dinv<<<(NT + TPB - 1) / TPB, TPB, 0, st[0]>>>(dinv);
    k_scan1<<<SCAN_BLK, 1024, 0, st[0]>>>(cnt, ptr, cur, bsum);
    k_scan2<<<1, 32, 0, st[0]>>>(bsum, boff, ptr);
    k_scan3<<<SCAN_BLK, 1024, 0, st[0]>>>(boff, ptr, cur);
    k_permute<<<(ET + TPB - 1) / TPB, TPB, 0, st[0]>>>(ei_all, w_all, dinv, cur, erow, enrm);

    // join branches, fork 4 timestep chains
    cudaStreamWaitEvent(st[0], evPrepG, 0);
    cudaEventRecord(evFork, st[0]);
    for (int i = 1; i < 4; i++) cudaStreamWaitEvent(st[i], evFork, 0);

    int aggBlocks = (Nn * 32 + TPB - 1) / TPB;
    dim3 ggrid((Nn + 127) / 128, Dd / 128);

    for (int t = 0; t < Tt; t++) {
        cudaStream_t s = st[t];
        __half* Hh = H[t];
        size_t xoff = (size_t)t * Nn * Dd;
        float* outT = out + xoff;

        for (int l = 0; l < 3; l++) {
            k_gemm_mma<<<ggrid, 256, GEMM_SMEM, s>>>(x + xoff,
                                                     wt + (size_t)l * Dd * Dd, Hh);
            bool last = (l == 2);
            k_aggregate<<<aggBlocks, TPB, 0, s>>>(ptr + (size_t)t * Nn, erow, enrm,
                                                  (const uint4*)Hh, dinv + (size_t)t * Nn,
                                                  (const float4*)bs[l],
                                                  last ? (float4*)outT : (float4*)nullptr,
                                                  last ? (uint4*)nullptr
                                                       : (uint4*)(x + xoff));
        }
    }

    // join all
    for (int i = 1; i < 4; i++) {
        cudaEventRecord(evJoin[i], st[i]);
        cudaStreamWaitEvent(st[0], evJoin[i], 0);
    }
}

// round 14
// speedup vs baseline: 1.2977x; 1.2153x over previous
#include <cuda_runtime.h>
#include <cuda_fp16.h>
#include <cstdint>

#define Tt 4
#define Nn 50000
#define Ee 800000
#define Dd 256
#define D4 64
#define NT (Tt * Nn)        // 200000
#define ET (Tt * Ee)        // 3200000
#define SCAN_BLK 49         // ceil(200000/4096)

// ---------------- scratch ----------------
__device__ __half g_x[(size_t)NT * Dd];      // ping buffer (fp16)
__device__ __half g_y[(size_t)NT * Dd];      // pong buffer (fp16)
__device__ float  g_T2[Dd * Dd];             // W2*W3 (fp32)
__device__ float  g_Wp32[Dd * Dd];           // W1*W2*W3 (fp32)
__device__ __half g_wtp[Dd * Dd];            // Wp^T (fp16) [N,K]
__device__ float  g_c1[Dd];                  // b1*W2*W3
__device__ float  g_c2[Dd];                  // b2*W3
__device__ float g_dinv[NT];
__device__ float g_sig[NT];                  // sigma = M*1
__device__ float g_msig[NT];                 // M*sigma
__device__ int   g_cnt[NT];
__device__ int   g_cur[NT];
__device__ int   g_ptr[NT + 1];
__device__ int   g_bsum[64];
__device__ int   g_boff[64];
__device__ int   g_erow[ET];
__device__ float g_enorm[ET];

// ---------------- helpers ----------------
__device__ __forceinline__ void h8f(uint4 v, float* f) {
    float2 p;
    p = __half22float2(*reinterpret_cast<__half2*>(&v.x)); f[0] = p.x; f[1] = p.y;
    p = __half22float2(*reinterpret_cast<__half2*>(&v.y)); f[2] = p.x; f[3] = p.y;
    p = __half22float2(*reinterpret_cast<__half2*>(&v.z)); f[4] = p.x; f[5] = p.y;
    p = __half22float2(*reinterpret_cast<__half2*>(&v.w)); f[6] = p.x; f[7] = p.y;
}
__device__ __forceinline__ uint32_t f2h2(float a, float b) {
    __half2 t = __floats2half2_rn(a, b);
    return *reinterpret_cast<uint32_t*>(&t);
}

// ---------------- batched prep ----------------
__global__ void k_init(float* __restrict__ deg, int* __restrict__ cnt,
                       float* __restrict__ sig) {
    int i = blockIdx.x * blockDim.x + threadIdx.x;
    if (i < NT) { deg[i] = 1.0f; cnt[i] = 0; sig[i] = 0.0f; }
}

__global__ void k_edge_prep(const int* __restrict__ ei_all, const float* __restrict__ w_all,
                            float* __restrict__ deg, int* __restrict__ cnt) {
    int ge = blockIdx.x * blockDim.x + threadIdx.x;
    if (ge < ET) {
        int t = ge / Ee, e = ge - t * Ee;
        int c = ei_all[(size_t)t * 2 * Ee + Ee + e];
        int gc = t * Nn + c;
        atomicAdd(&deg[gc], w_all[ge]);
        atomicAdd(&cnt[gc], 1);
    }
}

__global__ void k_finalize_dinv(float* __restrict__ deg) {
    int i = blockIdx.x * blockDim.x + threadIdx.x;
    if (i < NT) {
        float d = deg[i];
        deg[i] = (d > 0.0f) ? rsqrtf(d) : 0.0f;
    }
}

__global__ void __launch_bounds__(1024)
k_scan1(const int* __restrict__ cnt, int* __restrict__ ptr, int* __restrict__ cur,
        int* __restrict__ bsum) {
    __shared__ int wt[32];
    int tid = threadIdx.x, lane = tid & 31, wid = tid >> 5;
    int i0 = blockIdx.x * 4096 + tid * 4;
    int4 v = make_int4(0, 0, 0, 0);
    if (i0 + 3 < NT) v = *(const int4*)(cnt + i0);
    else {
        if (i0 < NT)     v.x = cnt[i0];
        if (i0 + 1 < NT) v.y = cnt[i0 + 1];
        if (i0 + 2 < NT) v.z = cnt[i0 + 2];
    }
    int tsum = v.x + v.y + v.z + v.w;
    int s = tsum;
#pragma unroll
    for (int off = 1; off < 32; off <<= 1) {
        int t = __shfl_up_sync(0xffffffffu, s, off);
        if (lane >= off) s += t;
    }
    if (lane == 31) wt[wid] = s;
    __syncthreads();
    if (wid == 0) {
        int ws = wt[lane];
#pragma unroll
        for (int off = 1; off < 32; off <<= 1) {
            int t = __shfl_up_sync(0xffffffffu, ws, off);
            if (lane >= off) ws += t;
        }
        wt[lane] = ws;
    }
    __syncthreads();
    int excl = s - tsum + (wid > 0 ? wt[wid - 1] : 0);
    int p = excl;
    if (i0 < NT)     { cur[i0] = p;     ptr[i0 + 1] = p + v.x; } p += v.x;
    if (i0 + 1 < NT) { cur[i0 + 1] = p; ptr[i0 + 2] = p + v.y; } p += v.y;
    if (i0 + 2 < NT) { cur[i0 + 2] = p; ptr[i0 + 3] = p + v.z; } p += v.z;
    if (i0 + 3 < NT) { cur[i0 + 3] = p; ptr[i0 + 4] = p + v.w; }
    if (tid == 1023) bsum[blockIdx.x] = excl + tsum;
}

__global__ void k_scan2(const int* __restrict__ bsum, int* __restrict__ boff,
                        int* __restrict__ ptr) {
    if (threadIdx.x == 0) {
        ptr[0] = 0;
        int run = 0;
        for (int b = 0; b < SCAN_BLK; b++) { boff[b] = run; run += bsum[b]; }
    }
}

__global__ void __launch_bounds__(1024)
k_scan3(const int* __restrict__ boff, int* __restrict__ ptr, int* __restrict__ cur) {
    int off = boff[blockIdx.x];
    int i0 = blockIdx.x * 4096 + threadIdx.x * 4;
#pragma unroll
    for (int k = 0; k < 4; k++) {
        int i = i0 + k;
        if (i < NT) { cur[i] += off; ptr[i + 1] += off; }
    }
}

// permute + sigma accumulation (sigma[c] += norm)
__global__ void k_permute(const int* __restrict__ ei_all, const float* __restrict__ w_all,
                          const float* __restrict__ dinv, int* __restrict__ cur,
                          int* __restrict__ erow, float* __restrict__ enorm,
                          float* __restrict__ sig) {
    int ge = blockIdx.x * blockDim.x + threadIdx.x;
    if (ge < ET) {
        int t = ge / Ee, e = ge - t * Ee;
        const int* base = ei_all + (size_t)t * 2 * Ee;
        int r = base[e], c = base[Ee + e];
        int gr = t * Nn + r, gc = t * Nn + c;
        float nm = dinv[gr] * w_all[ge] * dinv[gc];
        int pos = atomicAdd(&cur[gc], 1);
        erow[pos] = r;
        enorm[pos] = nm;
        atomicAdd(&sig[gc], nm);
    }
}

// sigma += dinv^2  (self loop term of M*1)
__global__ void k_sigma_fin(const float* __restrict__ dinv, float* __restrict__ sig) {
    int i = blockIdx.x * blockDim.x + threadIdx.x;
    if (i < NT) {
        float d = dinv[i];
        sig[i] += d * d;
    }
}

// msig = M * sigma  (scalar CSR pass)
__global__ void k_msigma(const int* __restrict__ ptr, const int* __restrict__ erow,
                         const float* __restrict__ enorm, const float* __restrict__ dinv,
                         const float* __restrict__ sig, float* __restrict__ msig) {
    int gc = blockIdx.x * blockDim.x + threadIdx.x;
    if (gc < NT) {
        int t = gc / Nn;
        float d = dinv[gc];
        float s = d * d * sig[gc];
        int jb = ptr[gc], je = ptr[gc + 1];
        const float* sbase = sig + (size_t)t * Nn;
        for (int j = jb; j < je; j++)
            s = fmaf(enorm[j], sbase[erow[j]], s);
        msig[gc] = s;
    }
}

// ---------------- fp32 SGEMM 256x256x256 (weight precompute) ----------------
__global__ void __launch_bounds__(256)
k_mm256(const float* __restrict__ A, const float* __restrict__ B, float* __restrict__ C) {
    const int BM = 128, BN = 128, BK = 16, TM = 8, TN = 8;
    __shared__ float As[BK][BM + 4];
    __shared__ float Bs[BK][BN];
    int tid = threadIdx.x;
    int m0 = blockIdx.x * BM, n0 = blockIdx.y * BN;
    int arow = tid >> 2, acol = (tid & 3) << 2;
    int brow = tid >> 5, bcol = (tid & 31) << 2;
    int tr = (tid >> 4) * TM, tc = (tid & 15) * TN;
    float acc[TM][TN] = {};
    for (int k0 = 0; k0 < Dd; k0 += BK) {
#pragma unroll
        for (int i = 0; i < 2; i++) {
            int r = arow + i * 64;
            float4 v = *(const float4*)(A + (size_t)(m0 + r) * Dd + k0 + acol);
            As[acol + 0][r] = v.x; As[acol + 1][r] = v.y;
            As[acol + 2][r] = v.z; As[acol + 3][r] = v.w;
        }
#pragma unroll
        for (int i = 0; i < 2; i++) {
            int r = brow + i * 8;
            *(float4*)&Bs[r][bcol] = *(const float4*)(B + (size_t)(k0 + r) * Dd + n0 + bcol);
        }
        __syncthreads();
#pragma unroll
        for (int kk = 0; kk < BK; kk++) {
            float ar[TM], br[TN];
#pragma unroll
            for (int i = 0; i < TM; i++) ar[i] = As[kk][tr + i];
#pragma unroll
            for (int j = 0; j < TN; j++) br[j] = Bs[kk][tc + j];
#pragma unroll
            for (int i = 0; i < TM; i++)
#pragma unroll
                for (int j = 0; j < TN; j++)
                    acc[i][j] = fmaf(ar[i], br[j], acc[i][j]);
        }
        __syncthreads();
    }
#pragma unroll
    for (int i = 0; i < TM; i++)
#pragma unroll
        for (int j = 0; j < TN; j += 4)
            *(float4*)(C + (size_t)(m0 + tr + i) * Dd + n0 + tc + j) =
                make_float4(acc[i][j], acc[i][j + 1], acc[i][j + 2], acc[i][j + 3]);
}

// c[n] = sum_a b[a] * M[a][n]
__global__ void k_vecmat(const float* __restrict__ b, const float* __restrict__ M,
                         float* __restrict__ c) {
    int n = blockIdx.x * blockDim.x + threadIdx.x;
    if (n < Dd) {
        float s = 0.0f;
        for (int a = 0; a < Dd; a++) s = fmaf(b[a], M[a * Dd + n], s);
        c[n] = s;
    }
}

// W^T fp16: wt[n*256+k] = fp16(W[k*256+n])
__global__ void k_wprep(const float* __restrict__ W, __half* __restrict__ wt) {
    int idx = blockIdx.x * blockDim.x + threadIdx.x;
    if (idx < Dd * Dd) {
        int n = idx >> 8, k = idx & 255;
        wt[idx] = __float2half_rn(W[k * Dd + n]);
    }
}

// embedding gather -> fp16 x
__global__ void k_gather(const int* __restrict__ ids, const float4* __restrict__ emb,
                         uint2* __restrict__ x) {
    int idx = blockIdx.x * blockDim.x + threadIdx.x;
    if (idx < NT * 64) {
        int i = idx >> 6, q = idx & 63;
        float4 v = emb[(size_t)ids[i] * 64 + q];
        x[idx] = make_uint2(f2h2(v.x, v.y), f2h2(v.z, v.w));
    }
}

// ---------------- aggregate: Y = M * X  (fp16 in/out, fp32 accum) ----------------
__global__ void __launch_bounds__(256)
k_aggregate(const int* __restrict__ ptr, const int* __restrict__ erow,
            const float* __restrict__ enorm, const uint4* __restrict__ src,
            const float* __restrict__ dinv, uint4* __restrict__ dst) {
    int warp = (blockIdx.x * blockDim.x + threadIdx.x) >> 5;
    int lane = threadIdx.x & 31;
    if (warp >= Nn) return;
    int node = warp;

    float s = dinv[node];
    s = s * s;
    float f[8], acc[8];
    h8f(src[(size_t)node * 32 + lane], f);
#pragma unroll
    for (int i = 0; i < 8; i++) acc[i] = s * f[i];

    int jb = ptr[node], je = ptr[node + 1];
    int j = jb;
    for (; j + 1 < je; j += 2) {
        int ra = erow[j], rb = erow[j + 1];
        float na = enorm[j], nb = enorm[j + 1];
        uint4 va = src[(size_t)ra * 32 + lane];
        uint4 vb = src[(size_t)rb * 32 + lane];
        float fa[8], fb[8];
        h8f(va, fa); h8f(vb, fb);
#pragma unroll
        for (int i = 0; i < 8; i++) acc[i] = fmaf(na, fa[i], acc[i]);
#pragma unroll
        for (int i = 0; i < 8; i++) acc[i] = fmaf(nb, fb[i], acc[i]);
    }
    if (j < je) {
        int r = erow[j];
        float nm = enorm[j];
        float fr[8];
        h8f(src[(size_t)r * 32 + lane], fr);
#pragma unroll
        for (int i = 0; i < 8; i++) acc[i] = fmaf(nm, fr[i], acc[i]);
    }

    dst[(size_t)node * 32 + lane] = make_uint4(f2h2(acc[0], acc[1]), f2h2(acc[2], acc[3]),
                                               f2h2(acc[4], acc[5]), f2h2(acc[6], acc[7]));
}

// ---------------- final GEMM: out = Y*Wp + msig*c1 + sig*c2 + b3 ----------------
__device__ __forceinline__ uint32_t swz(int row, int c) {
    return (uint32_t)(row * 64 + ((c ^ ((row >> 1) & 3)) << 4));
}

#define GEMM_SMEM 32768

__global__ void __launch_bounds__(256)
k_gemm_out(const __half* __restrict__ y, const __half* __restrict__ wtp,
           const float* __restrict__ sig, const float* __restrict__ msig,
           const float* __restrict__ c1, const float* __restrict__ c2,
           const float* __restrict__ b3, float* __restrict__ out) {
    extern __shared__ __align__(128) char sm[];

    const int tid = threadIdx.x;
    const int wid = tid >> 5, lane = tid & 31;
    const int m0 = blockIdx.x * 128, n0 = blockIdx.y * 128;
    const int mw = wid >> 2, nw = wid & 3;

    float acc[4][4][4] = {};

    auto issue = [&](int kc, int stage) {
        char* sbase = sm + stage * 16384;
#pragma unroll
        for (int i = 0; i < 4; i++) {
            int u = tid + i * 256;
            int tile = u >> 9, idx = u & 511;
            int row = idx >> 2, c = idx & 3;
            uint32_t dst = (uint32_t)__cvta_generic_to_shared(
                sbase + tile * 8192 + swz(row, c));
            if (tile == 0) {
                int gm = m0 + row;
                int ok = (gm < Nn);
                const void* src = y + (size_t)(ok ? gm : 0) * Dd + kc * 32 + c * 8;
                int sz = ok ? 16 : 0;
                asm volatile("cp.async.ca.shared.global [%0], [%1], 16, %2;"
                             :: "r"(dst), "l"(src), "r"(sz));
            } else {
                const void* src = wtp + (size_t)(n0 + row) * Dd + kc * 32 + c * 8;
                asm volatile("cp.async.ca.shared.global [%0], [%1], 16;"
                             :: "r"(dst), "l"(src));
            }
        }
        asm volatile("cp.async.commit_group;");
    };

    issue(0, 0);
    for (int it = 0; it < 8; it++) {
        int buf = it & 1;
        if (it + 1 < 8) {
            issue(it + 1, buf ^ 1);
            asm volatile("cp.async.wait_group 1;");
        } else {
            asm volatile("cp.async.wait_group 0;");
        }
        __syncthreads();
        char* pA = sm + buf * 16384;
        char* pB = pA + 8192;

#pragma unroll
        for (int ks = 0; ks < 2; ks++) {
            int ac = ks * 2 + ((lane >> 4) & 1);
            int brow = (lane & 7) + ((lane & 16) ? 8 : 0);
            int bc = ks * 2 + ((lane & 8) ? 1 : 0);
            uint32_t af[4][4];
#pragma unroll
            for (int mt = 0; mt < 4; mt++) {
                int row = mw * 64 + mt * 16 + (lane & 15);
                uint32_t a = (uint32_t)__cvta_generic_to_shared(pA + swz(row, ac));
                asm volatile("ldmatrix.sync.aligned.m8n8.x4.shared.b16 {%0,%1,%2,%3}, [%4];"
                             : "=r"(af[mt][0]), "=r"(af[mt][1]),
                               "=r"(af[mt][2]), "=r"(af[mt][3]) : "r"(a));
            }
            uint32_t bf[4][2];
#pragma unroll
            for (int ntp = 0; ntp < 2; ntp++) {
                int row = nw * 32 + ntp * 16 + brow;
                uint32_t b = (uint32_t)__cvta_generic_to_shared(pB + swz(row, bc));
                uint32_t r0, r1, r2, r3;
                asm volatile("ldmatrix.sync.aligned.m8n8.x4.shared.b16 {%0,%1,%2,%3}, [%4];"
                             : "=r"(r0), "=r"(r1), "=r"(r2), "=r"(r3) : "r"(b));
                bf[ntp * 2][0] = r0; bf[ntp * 2][1] = r1;
                bf[ntp * 2 + 1][0] = r2; bf[ntp * 2 + 1][1] = r3;
            }
#pragma unroll
            for (int mt = 0; mt < 4; mt++)
#pragma unroll
                for (int nt = 0; nt < 4; nt++) {
                    asm volatile(
                        "mma.sync.aligned.m16n8k16.row.col.f32.f16.f16.f32 "
                        "{%0,%1,%2,%3}, {%4,%5,%6,%7}, {%8,%9}, {%0,%1,%2,%3};"
                        : "+f"(acc[mt][nt][0]), "+f"(acc[mt][nt][1]),
                          "+f"(acc[mt][nt][2]), "+f"(acc[mt][nt][3])
                        : "r"(af[mt][0]), "r"(af[mt][1]), "r"(af[mt][2]), "r"(af[mt][3]),
                          "r"(bf[nt][0]), "r"(bf[nt][1]));
                }
        }
        __syncthreads();
    }

#pragma unroll
    for (int mt = 0; mt < 4; mt++) {
        int mm = m0 + mw * 64 + mt * 16 + (lane >> 2);
        float s1a = 0.f, s2a = 0.f, s1b = 0.f, s2b = 0.f;
        if (mm < Nn)     { s1a = msig[mm];     s2a = sig[mm]; }
        if (mm + 8 < Nn) { s1b = msig[mm + 8]; s2b = sig[mm + 8]; }
#pragma unroll
        for (int nt = 0; nt < 4; nt++) {
            int cc = n0 + nw * 32 + nt * 8 + 2 * (lane & 3);
            float e0 = c1[cc], e1 = c1[cc + 1];
            float g0 = c2[cc], g1 = c2[cc + 1];
            float h0 = b3[cc], h1 = b3[cc + 1];
            if (mm < Nn) {
                float o0 = acc[mt][nt][0] + s1a * e0 + s2a * g0 + h0;
                float o1 = acc[mt][nt][1] + s1a * e1 + s2a * g1 + h1;
                *(float2*)(out + (size_t)mm * Dd + cc) = make_float2(o0, o1);
            }
            if (mm + 8 < Nn) {
                float o0 = acc[mt][nt][2] + s1b * e0 + s2b * g0 + h0;
                float o1 = acc[mt][nt][3] + s1b * e1 + s2b * g1 + h1;
                *(float2*)(out + (size_t)(mm + 8) * Dd + cc) = make_float2(o0, o1);
            }
        }
    }
}

// ---------------- launch ----------------
extern "C" void kernel_launch(void* const* d_in, const int* in_sizes, int n_in,
                              void* d_out, int out_size) {
    const int*   ids_all = (const int*)d_in[0];
    const int*   ei_all  = (const int*)d_in[1];
    const float* w_all   = (const float*)d_in[2];
    const float* emb     = (const float*)d_in[3];
    const float* W1 = (const float*)d_in[4];
    const float* b1 = (const float*)d_in[5];
    const float* W2 = (const float*)d_in[6];
    const float* b2 = (const float*)d_in[7];
    const float* W3 = (const float*)d_in[8];
    const float* b3 = (const float*)d_in[9];
    float* out = (float*)d_out;

    void *px, *py, *pT2, *pWp, *pwtp, *pc1, *pc2, *pd, *psg, *pms,
         *pc, *pu, *pp, *pe, *pm, *pbs, *pbo;
    cudaGetSymbolAddress(&px,  g_x);
    cudaGetSymbolAddress(&py,  g_y);
    cudaGetSymbolAddress(&pT2, g_T2);
    cudaGetSymbolAddress(&pWp, g_Wp32);
    cudaGetSymbolAddress(&pwtp, g_wtp);
    cudaGetSymbolAddress(&pc1, g_c1);
    cudaGetSymbolAddress(&pc2, g_c2);
    cudaGetSymbolAddress(&pd,  g_dinv);
    cudaGetSymbolAddress(&psg, g_sig);
    cudaGetSymbolAddress(&pms, g_msig);
    cudaGetSymbolAddress(&pc,  g_cnt);
    cudaGetSymbolAddress(&pu,  g_cur);
    cudaGetSymbolAddress(&pp,  g_ptr);
    cudaGetSymbolAddress(&pe,  g_erow);
    cudaGetSymbolAddress(&pm,  g_enorm);
    cudaGetSymbolAddress(&pbs, g_bsum);
    cudaGetSymbolAddress(&pbo, g_boff);
    __half* x   = (__half*)px;
    __half* y   = (__half*)py;
    float*  T2  = (float*)pT2;
    float*  Wp  = (float*)pWp;
    __half* wtp = (__half*)pwtp;
    float*  c1  = (float*)pc1;
    float*  c2  = (float*)pc2;
    float* dinv = (float*)pd;
    float* sig  = (float*)psg;
    float* msig = (float*)pms;
    int* cnt = (int*)pc;
    int* cur = (int*)pu;
    int* ptr = (int*)pp;
    int* erow = (int*)pe;
    float* enrm = (float*)pm;
    int* bsum = (int*)pbs;
    int* boff = (int*)pbo;

    const int TPB = 256;
    static cudaStream_t st[4] = {nullptr, nullptr, nullptr, nullptr};
    static cudaEvent_t evStart = nullptr, evPrepG = nullptr;
    static cudaEvent_t evFork = nullptr, evJoin[4] = {nullptr, nullptr, nullptr, nullptr};
    if (!st[1]) {
        st[0] = (cudaStream_t)0;
        for (int i = 1; i < 4; i++) cudaStreamCreateWithFlags(&st[i], cudaStreamNonBlocking);
        cudaEventCreateWithFlags(&evStart, cudaEventDisableTiming);
        cudaEventCreateWithFlags(&evPrepG, cudaEventDisableTiming);
        cudaEventCreateWithFlags(&evFork, cudaEventDisableTiming);
        for (int i = 1; i < 4; i++) cudaEventCreateWithFlags(&evJoin[i], cudaEventDisableTiming);
        cudaFuncSetAttribute(k_gemm_out, cudaFuncAttributeMaxDynamicSharedMemorySize,
                             GEMM_SMEM);
    }

    // ---- prep: two parallel branches ----
    cudaEventRecord(evStart, st[0]);
    cudaStreamWaitEvent(st[1], evStart, 0);

    // branch A (st[1]): weight composition + bias vectors + gather
    dim3 mmgrid(2, 2);
    k_mm256<<<mmgrid, 256, 0, st[1]>>>(W2, W3, T2);          // T2 = W2*W3
    k_mm256<<<mmgrid, 256, 0, st[1]>>>(W1, T2, Wp);          // Wp = W1*T2
    k_wprep<<<(Dd * Dd + TPB - 1) / TPB, TPB, 0, st[1]>>>(Wp, wtp);
    k_vecmat<<<1, 256, 0, st[1]>>>(b1, T2, c1);              // c1 = b1*W2*W3
    k_vecmat<<<1, 256, 0, st[1]>>>(b2, W3, c2);              // c2 = b2*W3
    k_gather<<<(NT * 64 + TPB - 1) / TPB, TPB, 0, st[1]>>>(ids_all, (const float4*)emb,
                                                           (uint2*)x);
    cudaEventRecord(evPrepG, st[1]);

    // branch B (st[0]): edge chain + sigma/msigma
    k_init<<<(NT + TPB - 1) / TPB, TPB, 0, st[0]>>>(dinv, cnt, sig);
    k_edge_prep<<<(ET + TPB - 1) / TPB, TPB, 0, st[0]>>>(ei_all, w_all, dinv, cnt);
    k_finalize_dinv<<<(NT + TPB - 1) / TPB, TPB, 0, st[0]>>>(dinv);
    k_scan1<<<SCAN_BLK, 1024, 0, st[0]>>>(cnt, ptr, cur, bsum);
    k_scan2<<<1, 32, 0, st[0]>>>(bsum, boff, ptr);
    k_scan3<<<SCAN_BLK, 1024, 0, st[0]>>>(boff, ptr, cur);
    k_permute<<<(ET + TPB - 1) / TPB, TPB, 0, st[0]>>>(ei_all, w_all, dinv, cur,
                                                       erow, enrm, sig);
    k_sigma_fin<<<(NT + TPB - 1) / TPB, TPB, 0, st[0]>>>(dinv, sig);
    k_msigma<<<(NT + TPB - 1) / TPB, TPB, 0, st[0]>>>(ptr, erow, enrm, dinv, sig, msig);

    // join branches, fork 4 timestep chains
    cudaStreamWaitEvent(st[0], evPrepG, 0);
    cudaEventRecord(evFork, st[0]);
    for (int i = 1; i < 4; i++) cudaStreamWaitEvent(st[i], evFork, 0);

    int aggBlocks = (Nn * 32 + TPB - 1) / TPB;
    dim3 ggrid((Nn + 127) / 128, Dd / 128);

    for (int t = 0; t < Tt; t++) {
        cudaStream_t s = st[t];
        size_t off = (size_t)t * Nn * Dd;
        __half* xt = x + off;
        __half* yt = y + off;
        const int* ptrT = ptr + (size_t)t * Nn;
        const float* dinvT = dinv + (size_t)t * Nn;
        float* outT = out + off;

        // Y1 = M*X ; Y2 = M*Y1 ; Y3 = M*Y2   (ping-pong x<->y)
        k_aggregate<<<aggBlocks, TPB, 0, s>>>(ptrT, erow, enrm, (const uint4*)xt,
                                              dinvT, (uint4*)yt);
        k_aggregate<<<aggBlocks, TPB, 0, s>>>(ptrT, erow, enrm, (const uint4*)yt,
                                              dinvT, (uint4*)xt);
        k_aggregate<<<aggBlocks, TPB, 0, s>>>(ptrT, erow, enrm, (const uint4*)xt,
                                              dinvT, (uint4*)yt);
        // out = Y3*Wp + msig*c1 + sig*c2 + b3
        k_gemm_out<<<ggrid, 256, GEMM_SMEM, s>>>(yt, wtp,
                                                 sig + (size_t)t * Nn,
                                                 msig + (size_t)t * Nn,
                                                 c1, c2, b3, outT);
    }

    // join all
    for (int i = 1; i < 4; i++) {
        cudaEventRecord(evJoin[i], st[i]);
        cudaStreamWaitEvent(st[0], evJoin[i], 0);
    }
}

// round 16
// speedup vs baseline: 1.3066x; 1.0068x over previous
#include <cuda_runtime.h>
#include <cuda_fp16.h>
#include <cstdint>

#define Tt 4
#define Nn 50000
#define Ee 800000
#define Dd 256
#define D4 64
#define NT (Tt * Nn)        // 200000
#define ET (Tt * Ee)        // 3200000
#define SCAN_BLK 49         // ceil(200000/4096)

// ---------------- scratch ----------------
__device__ __half g_x[(size_t)NT * Dd];      // ping (fp16)
__device__ __half g_y[(size_t)NT * Dd];      // pong (fp16)
__device__ float  g_T2[Dd * Dd];             // W2*W3
__device__ float  g_Wp32[Dd * Dd];           // W1*W2*W3
__device__ __half g_wtp[Dd * Dd];            // Wp^T fp16 [N,K]
__device__ float  g_c1[Dd];                  // b1*W2*W3
__device__ float  g_c2[Dd];                  // b2*W3
__device__ float g_dinv[NT];
__device__ float g_sig[NT];
__device__ float g_msig[NT];
__device__ int   g_cnt[NT];
__device__ int   g_cur[NT];
__device__ int   g_ptr[NT + 1];
__device__ int   g_bsum[64];
__device__ int   g_boff[64];
__device__ int   g_erow[ET];
__device__ float g_enorm[ET];

// ---------------- helpers ----------------
__device__ __forceinline__ void h8f(uint4 v, float* f) {
    float2 p;
    p = __half22float2(*reinterpret_cast<__half2*>(&v.x)); f[0] = p.x; f[1] = p.y;
    p = __half22float2(*reinterpret_cast<__half2*>(&v.y)); f[2] = p.x; f[3] = p.y;
    p = __half22float2(*reinterpret_cast<__half2*>(&v.z)); f[4] = p.x; f[5] = p.y;
    p = __half22float2(*reinterpret_cast<__half2*>(&v.w)); f[6] = p.x; f[7] = p.y;
}
__device__ __forceinline__ uint32_t f2h2(float a, float b) {
    __half2 t = __floats2half2_rn(a, b);
    return *reinterpret_cast<uint32_t*>(&t);
}

// ---------------- batched prep ----------------
__global__ void k_init(float* __restrict__ deg, int* __restrict__ cnt,
                       float* __restrict__ sig) {
    int i = blockIdx.x * blockDim.x + threadIdx.x;
    if (i < NT) { deg[i] = 1.0f; cnt[i] = 0; sig[i] = 0.0f; }
}

__global__ void k_edge_prep(const int* __restrict__ ei_all, const float* __restrict__ w_all,
                            float* __restrict__ deg, int* __restrict__ cnt) {
    int ge = blockIdx.x * blockDim.x + threadIdx.x;
    if (ge < ET) {
        int t = ge / Ee, e = ge - t * Ee;
        int c = ei_all[(size_t)t * 2 * Ee + Ee + e];
        int gc = t * Nn + c;
        atomicAdd(&deg[gc], w_all[ge]);
        atomicAdd(&cnt[gc], 1);
    }
}

__global__ void k_finalize_dinv(float* __restrict__ deg) {
    int i = blockIdx.x * blockDim.x + threadIdx.x;
    if (i < NT) {
        float d = deg[i];
        deg[i] = (d > 0.0f) ? rsqrtf(d) : 0.0f;
    }
}

__global__ void __launch_bounds__(1024)
k_scan1(const int* __restrict__ cnt, int* __restrict__ ptr, int* __restrict__ cur,
        int* __restrict__ bsum) {
    __shared__ int wt[32];
    int tid = threadIdx.x, lane = tid & 31, wid = tid >> 5;
    int i0 = blockIdx.x * 4096 + tid * 4;
    int4 v = make_int4(0, 0, 0, 0);
    if (i0 + 3 < NT) v = *(const int4*)(cnt + i0);
    else {
        if (i0 < NT)     v.x = cnt[i0];
        if (i0 + 1 < NT) v.y = cnt[i0 + 1];
        if (i0 + 2 < NT) v.z = cnt[i0 + 2];
    }
    int tsum = v.x + v.y + v.z + v.w;
    int s = tsum;
#pragma unroll
    for (int off = 1; off < 32; off <<= 1) {
        int t = __shfl_up_sync(0xffffffffu, s, off);
        if (lane >= off) s += t;
    }
    if (lane == 31) wt[wid] = s;
    __syncthreads();
    if (wid == 0) {
        int ws = wt[lane];
#pragma unroll
        for (int off = 1; off < 32; off <<= 1) {
            int t = __shfl_up_sync(0xffffffffu, ws, off);
            if (lane >= off) ws += t;
        }
        wt[lane] = ws;
    }
    __syncthreads();
    int excl = s - tsum + (wid > 0 ? wt[wid - 1] : 0);
    int p = excl;
    if (i0 < NT)     { cur[i0] = p;     ptr[i0 + 1] = p + v.x; } p += v.x;
    if (i0 + 1 < NT) { cur[i0 + 1] = p; ptr[i0 + 2] = p + v.y; } p += v.y;
    if (i0 + 2 < NT) { cur[i0 + 2] = p; ptr[i0 + 3] = p + v.z; } p += v.z;
    if (i0 + 3 < NT) { cur[i0 + 3] = p; ptr[i0 + 4] = p + v.w; }
    if (tid == 1023) bsum[blockIdx.x] = excl + tsum;
}

__global__ void k_scan2(const int* __restrict__ bsum, int* __restrict__ boff,
                        int* __restrict__ ptr) {
    if (threadIdx.x == 0) {
        ptr[0] = 0;
        int run = 0;
        for (int b = 0; b < SCAN_BLK; b++) { boff[b] = run; run += bsum[b]; }
    }
}

__global__ void __launch_bounds__(1024)
k_scan3(const int* __restrict__ boff, int* __restrict__ ptr, int* __restrict__ cur) {
    int off = boff[blockIdx.x];
    int i0 = blockIdx.x * 4096 + threadIdx.x * 4;
#pragma unroll
    for (int k = 0; k < 4; k++) {
        int i = i0 + k;
        if (i < NT) { cur[i] += off; ptr[i + 1] += off; }
    }
}

__global__ void k_permute(const int* __restrict__ ei_all, const float* __restrict__ w_all,
                          const float* __restrict__ dinv, int* __restrict__ cur,
                          int* __restrict__ erow, float* __restrict__ enorm,
                          float* __restrict__ sig) {
    int ge = blockIdx.x * blockDim.x + threadIdx.x;
    if (ge < ET) {
        int t = ge / Ee, e = ge - t * Ee;
        const int* base = ei_all + (size_t)t * 2 * Ee;
        int r = base[e], c = base[Ee + e];
        int gr = t * Nn + r, gc = t * Nn + c;
        float nm = dinv[gr] * w_all[ge] * dinv[gc];
        int pos = atomicAdd(&cur[gc], 1);
        erow[pos] = r;
        enorm[pos] = nm;
        atomicAdd(&sig[gc], nm);
    }
}

__global__ void k_sigma_fin(const float* __restrict__ dinv, float* __restrict__ sig) {
    int i = blockIdx.x * blockDim.x + threadIdx.x;
    if (i < NT) {
        float d = dinv[i];
        sig[i] += d * d;
    }
}

__global__ void k_msigma(const int* __restrict__ ptr, const int* __restrict__ erow,
                         const float* __restrict__ enorm, const float* __restrict__ dinv,
                         const float* __restrict__ sig, float* __restrict__ msig) {
    int gc = blockIdx.x * blockDim.x + threadIdx.x;
    if (gc < NT) {
        int t = gc / Nn;
        float d = dinv[gc];
        float s = d * d * sig[gc];
        int jb = ptr[gc], je = ptr[gc + 1];
        const float* sbase = sig + (size_t)t * Nn;
        for (int j = jb; j < je; j++)
            s = fmaf(enorm[j], sbase[erow[j]], s);
        msig[gc] = s;
    }
}

// ---------------- weight precompute ----------------
__global__ void __launch_bounds__(256)
k_mm256(const float* __restrict__ A, const float* __restrict__ B, float* __restrict__ C) {
    const int BM = 128, BN = 128, BK = 16, TM = 8, TN = 8;
    __shared__ float As[BK][BM + 4];
    __shared__ float Bs[BK][BN];
    int tid = threadIdx.x;
    int m0 = blockIdx.x * BM, n0 = blockIdx.y * BN;
    int arow = tid >> 2, acol = (tid & 3) << 2;
    int brow = tid >> 5, bcol = (tid & 31) << 2;
    int tr = (tid >> 4) * TM, tc = (tid & 15) * TN;
    float acc[TM][TN] = {};
    for (int k0 = 0; k0 < Dd; k0 += BK) {
#pragma unroll
        for (int i = 0; i < 2; i++) {
            int r = arow + i * 64;
            float4 v = *(const float4*)(A + (size_t)(m0 + r) * Dd + k0 + acol);
            As[acol + 0][r] = v.x; As[acol + 1][r] = v.y;
            As[acol + 2][r] = v.z; As[acol + 3][r] = v.w;
        }
#pragma unroll
        for (int i = 0; i < 2; i++) {
            int r = brow + i * 8;
            *(float4*)&Bs[r][bcol] = *(const float4*)(B + (size_t)(k0 + r) * Dd + n0 + bcol);
        }
        __syncthreads();
#pragma unroll
        for (int kk = 0; kk < BK; kk++) {
            float ar[TM], br[TN];
#pragma unroll
            for (int i = 0; i < TM; i++) ar[i] = As[kk][tr + i];
#pragma unroll
            for (int j = 0; j < TN; j++) br[j] = Bs[kk][tc + j];
#pragma unroll
            for (int i = 0; i < TM; i++)
#pragma unroll
                for (int j = 0; j < TN; j++)
                    acc[i][j] = fmaf(ar[i], br[j], acc[i][j]);
        }
        __syncthreads();
    }
#pragma unroll
    for (int i = 0; i < TM; i++)
#pragma unroll
        for (int j = 0; j < TN; j += 4)
            *(float4*)(C + (size_t)(m0 + tr + i) * Dd + n0 + tc + j) =
                make_float4(acc[i][j], acc[i][j + 1], acc[i][j + 2], acc[i][j + 3]);
}

// c[n] = sum_a b[a]*M[a][n] ; one warp per output column
__global__ void k_vecmat(const float* __restrict__ b, const float* __restrict__ M,
                         float* __restrict__ c) {
    int n = blockIdx.x * 8 + (threadIdx.x >> 5);
    int lane = threadIdx.x & 31;
    if (n >= Dd) return;
    float s = 0.0f;
    for (int a = lane; a < Dd; a += 32)
        s = fmaf(b[a], M[a * Dd + n], s);
#pragma unroll
    for (int off = 16; off > 0; off >>= 1)
        s += __shfl_down_sync(0xffffffffu, s, off);
    if (lane == 0) c[n] = s;
}

__global__ void k_wprep(const float* __restrict__ W, __half* __restrict__ wt) {
    int idx = blockIdx.x * blockDim.x + threadIdx.x;
    if (idx < Dd * Dd) {
        int n = idx >> 8, k = idx & 255;
        wt[idx] = __float2half_rn(W[k * Dd + n]);
    }
}

__global__ void k_gather(const int* __restrict__ ids, const float4* __restrict__ emb,
                         uint2* __restrict__ x) {
    int idx = blockIdx.x * blockDim.x + threadIdx.x;
    if (idx < NT * 64) {
        int i = idx >> 6, q = idx & 63;
        float4 v = emb[(size_t)ids[i] * 64 + q];
        x[idx] = make_uint2(f2h2(v.x, v.y), f2h2(v.z, v.w));
    }
}

// ---------------- aggregate: Y = M * X ----------------
__global__ void __launch_bounds__(256)
k_aggregate(const int* __restrict__ ptr, const int* __restrict__ erow,
            const float* __restrict__ enorm, const uint4* __restrict__ src,
            const float* __restrict__ dinv, uint4* __restrict__ dst) {
    int warp = (blockIdx.x * blockDim.x + threadIdx.x) >> 5;
    int lane = threadIdx.x & 31;
    if (warp >= Nn) return;
    int node = warp;

    float s = dinv[node];
    s = s * s;
    float f[8], acc[8];
    h8f(src[(size_t)node * 32 + lane], f);
#pragma unroll
    for (int i = 0; i < 8; i++) acc[i] = s * f[i];

    int jb = ptr[node], je = ptr[node + 1];
    int j = jb;
    for (; j + 1 < je; j += 2) {
        int ra = erow[j], rb = erow[j + 1];
        float na = enorm[j], nb = enorm[j + 1];
        uint4 va = src[(size_t)ra * 32 + lane];
        uint4 vb = src[(size_t)rb * 32 + lane];
        float fa[8], fb[8];
        h8f(va, fa); h8f(vb, fb);
#pragma unroll
        for (int i = 0; i < 8; i++) acc[i] = fmaf(na, fa[i], acc[i]);
#pragma unroll
        for (int i = 0; i < 8; i++) acc[i] = fmaf(nb, fb[i], acc[i]);
    }
    if (j < je) {
        int r = erow[j];
        float nm = enorm[j];
        float fr[8];
        h8f(src[(size_t)r * 32 + lane], fr);
#pragma unroll
        for (int i = 0; i < 8; i++) acc[i] = fmaf(nm, fr[i], acc[i]);
    }

    dst[(size_t)node * 32 + lane] = make_uint4(f2h2(acc[0], acc[1]), f2h2(acc[2], acc[3]),
                                               f2h2(acc[4], acc[5]), f2h2(acc[6], acc[7]));
}

// ---------------- final GEMM + bias epilogue ----------------
__device__ __forceinline__ uint32_t swz(int row, int c) {
    return (uint32_t)(row * 64 + ((c ^ ((row >> 1) & 3)) << 4));
}

#define GEMM_SMEM 32768

__global__ void __launch_bounds__(256)
k_gemm_out(const __half* __restrict__ y, const __half* __restrict__ wtp,
           const float* __restrict__ sig, const float* __restrict__ msig,
           const float* __restrict__ c1, const float* __restrict__ c2,
           const float* __restrict__ b3, float* __restrict__ out) {
    extern __shared__ __align__(128) char sm[];

    const int tid = threadIdx.x;
    const int wid = tid >> 5, lane = tid & 31;
    const int m0 = blockIdx.x * 128, n0 = blockIdx.y * 128;
    const int mw = wid >> 2, nw = wid & 3;

    float acc[4][4][4] = {};

    auto issue = [&](int kc, int stage) {
        char* sbase = sm + stage * 16384;
#pragma unroll
        for (int i = 0; i < 4; i++) {
            int u = tid + i * 256;
            int tile = u >> 9, idx = u & 511;
            int row = idx >> 2, c = idx & 3;
            uint32_t dst = (uint32_t)__cvta_generic_to_shared(
                sbase + tile * 8192 + swz(row, c));
            if (tile == 0) {
                int gm = m0 + row;
                int ok = (gm < Nn);
                const void* src = y + (size_t)(ok ? gm : 0) * Dd + kc * 32 + c * 8;
                int sz = ok ? 16 : 0;
                asm volatile("cp.async.ca.shared.global [%0], [%1], 16, %2;"
                             :: "r"(dst), "l"(src), "r"(sz));
            } else {
                const void* src = wtp + (size_t)(n0 + row) * Dd + kc * 32 + c * 8;
                asm volatile("cp.async.ca.shared.global [%0], [%1], 16;"
                             :: "r"(dst), "l"(src));
            }
        }
        asm volatile("cp.async.commit_group;");
    };

    issue(0, 0);
    for (int it = 0; it < 8; it++) {
        int buf = it & 1;
        if (it + 1 < 8) {
            issue(it + 1, buf ^ 1);
            asm volatile("cp.async.wait_group 1;");
        } else {
            asm volatile("cp.async.wait_group 0;");
        }
        __syncthreads();
        char* pA = sm + buf * 16384;
        char* pB = pA + 8192;

#pragma unroll
        for (int ks = 0; ks < 2; ks++) {
            int ac = ks * 2 + ((lane >> 4) & 1);
            int brow = (lane & 7) + ((lane & 16) ? 8 : 0);
            int bc = ks * 2 + ((lane & 8) ? 1 : 0);
            uint32_t af[4][4];
#pragma unroll
            for (int mt = 0; mt < 4; mt++) {
                int row = mw * 64 + mt * 16 + (lane & 15);
                uint32_t a = (uint32_t)__cvta_generic_to_shared(pA + swz(row, ac));
                asm volatile("ldmatrix.sync.aligned.m8n8.x4.shared.b16 {%0,%1,%2,%3}, [%4];"
                             : "=r"(af[mt][0]), "=r"(af[mt][1]),
                               "=r"(af[mt][2]), "=r"(af[mt][3]) : "r"(a));
            }
            uint32_t bf[4][2];
#pragma unroll
            for (int ntp = 0; ntp < 2; ntp++) {
                int row = nw * 32 + ntp * 16 + brow;
                uint32_t b = (uint32_t)__cvta_generic_to_shared(pB + swz(row, bc));
                uint32_t r0, r1, r2, r3;
                asm volatile("ldmatrix.sync.aligned.m8n8.x4.shared.b16 {%0,%1,%2,%3}, [%4];"
                             : "=r"(r0), "=r"(r1), "=r"(r2), "=r"(r3) : "r"(b));
                bf[ntp * 2][0] = r0; bf[ntp * 2][1] = r1;
                bf[ntp * 2 + 1][0] = r2; bf[ntp * 2 + 1][1] = r3;
            }
#pragma unroll
            for (int mt = 0; mt < 4; mt++)
#pragma unroll
                for (int nt = 0; nt < 4; nt++) {
                    asm volatile(
                        "mma.sync.aligned.m16n8k16.row.col.f32.f16.f16.f32 "
                        "{%0,%1,%2,%3}, {%4,%5,%6,%7}, {%8,%9}, {%0,%1,%2,%3};"
                        : "+f"(acc[mt][nt][0]), "+f"(acc[mt][nt][1]),
                          "+f"(acc[mt][nt][2]), "+f"(acc[mt][nt][3])
                        : "r"(af[mt][0]), "r"(af[mt][1]), "r"(af[mt][2]), "r"(af[mt][3]),
                          "r"(bf[nt][0]), "r"(bf[nt][1]));
                }
        }
        __syncthreads();
    }

#pragma unroll
    for (int mt = 0; mt < 4; mt++) {
        int mm = m0 + mw * 64 + mt * 16 + (lane >> 2);
        float s1a = 0.f, s2a = 0.f, s1b = 0.f, s2b = 0.f;
        if (mm < Nn)     { s1a = msig[mm];     s2a = sig[mm]; }
        if (mm + 8 < Nn) { s1b = msig[mm + 8]; s2b = sig[mm + 8]; }
#pragma unroll
        for (int nt = 0; nt < 4; nt++) {
            int cc = n0 + nw * 32 + nt * 8 + 2 * (lane & 3);
            float e0 = c1[cc], e1 = c1[cc + 1];
            float g0 = c2[cc], g1 = c2[cc + 1];
            float h0 = b3[cc], h1 = b3[cc + 1];
            if (mm < Nn) {
                float o0 = acc[mt][nt][0] + s1a * e0 + s2a * g0 + h0;
                float o1 = acc[mt][nt][1] + s1a * e1 + s2a * g1 + h1;
                *(float2*)(out + (size_t)mm * Dd + cc) = make_float2(o0, o1);
            }
            if (mm + 8 < Nn) {
                float o0 = acc[mt][nt][2] + s1b * e0 + s2b * g0 + h0;
                float o1 = acc[mt][nt][3] + s1b * e1 + s2b * g1 + h1;
                *(float2*)(out + (size_t)(mm + 8) * Dd + cc) = make_float2(o0, o1);
            }
        }
    }
}

// ---------------- launch (r14 topology, 2 execution streams) ----------------
extern "C" void kernel_launch(void* const* d_in, const int* in_sizes, int n_in,
                              void* d_out, int out_size) {
    const int*   ids_all = (const int*)d_in[0];
    const int*   ei_all  = (const int*)d_in[1];
    const float* w_all   = (const float*)d_in[2];
    const float* emb     = (const float*)d_in[3];
    const float* W1 = (const float*)d_in[4];
    const float* b1 = (const float*)d_in[5];
    const float* W2 = (const float*)d_in[6];
    const float* b2 = (const float*)d_in[7];
    const float* W3 = (const float*)d_in[8];
    const float* b3 = (const float*)d_in[9];
    float* out = (float*)d_out;

    void *px, *py, *pT2, *pWp, *pwtp, *pc1, *pc2, *pd, *psg, *pms,
         *pc, *pu, *pp, *pe, *pm, *pbs, *pbo;
    cudaGetSymbolAddress(&px,  g_x);
    cudaGetSymbolAddress(&py,  g_y);
    cudaGetSymbolAddress(&pT2, g_T2);
    cudaGetSymbolAddress(&pWp, g_Wp32);
    cudaGetSymbolAddress(&pwtp, g_wtp);
    cudaGetSymbolAddress(&pc1, g_c1);
    cudaGetSymbolAddress(&pc2, g_c2);
    cudaGetSymbolAddress(&pd,  g_dinv);
    cudaGetSymbolAddress(&psg, g_sig);
    cudaGetSymbolAddress(&pms, g_msig);
    cudaGetSymbolAddress(&pc,  g_cnt);
    cudaGetSymbolAddress(&pu,  g_cur);
    cudaGetSymbolAddress(&pp,  g_ptr);
    cudaGetSymbolAddress(&pe,  g_erow);
    cudaGetSymbolAddress(&pm,  g_enorm);
    cudaGetSymbolAddress(&pbs, g_bsum);
    cudaGetSymbolAddress(&pbo, g_boff);
    __half* x   = (__half*)px;
    __half* y   = (__half*)py;
    float*  T2  = (float*)pT2;
    float*  Wp  = (float*)pWp;
    __half* wtp = (__half*)pwtp;
    float*  c1  = (float*)pc1;
    float*  c2  = (float*)pc2;
    float* dinv = (float*)pd;
    float* sig  = (float*)psg;
    float* msig = (float*)pms;
    int* cnt = (int*)pc;
    int* cur = (int*)pu;
    int* ptr = (int*)pp;
    int* erow = (int*)pe;
    float* enrm = (float*)pm;
    int* bsum = (int*)pbs;
    int* boff = (int*)pbo;

    const int TPB = 256;
    static cudaStream_t st1 = nullptr;
    static cudaEvent_t evStart = nullptr, evPrepG = nullptr, evFork = nullptr,
                       evJoin = nullptr;
    if (!st1) {
        cudaStreamCreateWithFlags(&st1, cudaStreamNonBlocking);
        cudaEventCreateWithFlags(&evStart, cudaEventDisableTiming);
        cudaEventCreateWithFlags(&evPrepG, cudaEventDisableTiming);
        cudaEventCreateWithFlags(&evFork, cudaEventDisableTiming);
        cudaEventCreateWithFlags(&evJoin, cudaEventDisableTiming);
        cudaFuncSetAttribute(k_gemm_out, cudaFuncAttributeMaxDynamicSharedMemorySize,
                             GEMM_SMEM);
    }

    // ---- prep: two parallel branches (r14 pattern) ----
    cudaEventRecord(evStart, (cudaStream_t)0);
    cudaStreamWaitEvent(st1, evStart, 0);

    // branch A (st1): weight composition + bias vectors + gather
    dim3 mmgrid(2, 2);
    k_mm256<<<mmgrid, 256, 0, st1>>>(W2, W3, T2);
    k_mm256<<<mmgrid, 256, 0, st1>>>(W1, T2, Wp);
    k_wprep<<<(Dd * Dd + TPB - 1) / TPB, TPB, 0, st1>>>(Wp, wtp);
    k_vecmat<<<32, 256, 0, st1>>>(b1, T2, c1);
    k_vecmat<<<32, 256, 0, st1>>>(b2, W3, c2);
    k_gather<<<(NT * 64 + TPB - 1) / TPB, TPB, 0, st1>>>(ids_all, (const float4*)emb,
                                                         (uint2*)x);
    cudaEventRecord(evPrepG, st1);

    // branch B (default): edge chain + sigma/msigma
    k_init<<<(NT + TPB - 1) / TPB, TPB>>>(dinv, cnt, sig);
    k_edge_prep<<<(ET + TPB - 1) / TPB, TPB>>>(ei_all, w_all, dinv, cnt);
    k_finalize_dinv<<<(NT + TPB - 1) / TPB, TPB>>>(dinv);
    k_scan1<<<SCAN_BLK, 1024>>>(cnt, ptr, cur, bsum);
    k_scan2<<<1, 32>>>(bsum, boff, ptr);
    k_scan3<<<SCAN_BLK, 1024>>>(boff, ptr, cur);
    k_permute<<<(ET + TPB - 1) / TPB, TPB>>>(ei_all, w_all, dinv, cur, erow, enrm, sig);
    k_sigma_fin<<<(NT + TPB - 1) / TPB, TPB>>>(dinv, sig);
    k_msigma<<<(NT + TPB - 1) / TPB, TPB>>>(ptr, erow, enrm, dinv, sig, msig);

    // join branches, fork 2 chains (each owns 2 timesteps sequentially)
    cudaStreamWaitEvent((cudaStream_t)0, evPrepG, 0);
    cudaEventRecord(evFork, (cudaStream_t)0);
    cudaStreamWaitEvent(st1, evFork, 0);

    int aggBlocks = (Nn * 32 + TPB - 1) / TPB;
    dim3 ggrid((Nn + 127) / 128, Dd / 128);

    // schedule: stream0 -> t=0 then t=2 ; stream1 -> t=1 then t=3
    for (int wave = 0; wave < 2; wave++) {
        for (int lane2 = 0; lane2 < 2; lane2++) {
            int t = wave * 2 + lane2;
            cudaStream_t s = (lane2 == 0) ? (cudaStream_t)0 : st1;
            size_t off = (size_t)t * Nn * Dd;
            __half* xt = x + off;
            __half* yt = y + off;
            const int* ptrT = ptr + (size_t)t * Nn;
            const float* dinvT = dinv + (size_t)t * Nn;

            k_aggregate<<<aggBlocks, TPB, 0, s>>>(ptrT, erow, enrm, (const uint4*)xt,
                                                  dinvT, (uint4*)yt);
            k_aggregate<<<aggBlocks, TPB, 0, s>>>(ptrT, erow, enrm, (const uint4*)yt,
                                                  dinvT, (uint4*)xt);
            k_aggregate<<<aggBlocks, TPB, 0, s>>>(ptrT, erow, enrm, (const uint4*)xt,
                                                  dinvT, (uint4*)yt);
            k_gemm_out<<<ggrid, 256, GEMM_SMEM, s>>>(yt, wtp,
                                                     sig + (size_t)t * Nn,
                                                     msig + (size_t)t * Nn,
                                                     c1, c2, b3, out + off);
        }
    }

    // single join at the very end
    cudaEventRecord(evJoin, st1);
    cudaStreamWaitEvent((cudaStream_t)0, evJoin, 0);
}

// round 17
// speedup vs baseline: 1.3258x; 1.0147x over previous
#include <cuda_runtime.h>
#include <cuda_fp16.h>
#include <cstdint>

#define Tt 4
#define Nn 50000
#define Ee 800000
#define Dd 256
#define NT (Tt * Nn)
#define NB (2 * Nn)          // nodes per batch (2 timesteps)
#define EB (2 * Ee)          // edges per batch
#define SCAN_BLKB 25         // ceil(100000/4096)

// ---------------- scratch ----------------
__device__ __half g_x[(size_t)NT * Dd];
__device__ __half g_y[(size_t)NT * Dd];
__device__ float  g_T2[Dd * Dd];
__device__ float  g_Wp32[Dd * Dd];
__device__ __half g_wtp[Dd * Dd];
__device__ float  g_c1[Dd];
__device__ float  g_c2[Dd];
__device__ float g_dinv[NT];
__device__ float g_sig[NT];
__device__ float g_msig[NT];
__device__ int   g_cnt[NT];
__device__ int   g_cur[NT];
__device__ int   g_ptr[2 * (NB + 1)];
__device__ int   g_bsum[2 * 32];
__device__ int   g_boff[2 * 32];
__device__ int   g_erow[(size_t)2 * EB];
__device__ float g_enorm[(size_t)2 * EB];

// ---------------- helpers ----------------
__device__ __forceinline__ void h8f(uint4 v, float* f) {
    float2 p;
    p = __half22float2(*reinterpret_cast<__half2*>(&v.x)); f[0] = p.x; f[1] = p.y;
    p = __half22float2(*reinterpret_cast<__half2*>(&v.y)); f[2] = p.x; f[3] = p.y;
    p = __half22float2(*reinterpret_cast<__half2*>(&v.z)); f[4] = p.x; f[5] = p.y;
    p = __half22float2(*reinterpret_cast<__half2*>(&v.w)); f[6] = p.x; f[7] = p.y;
}
__device__ __forceinline__ uint32_t f2h2(float a, float b) {
    __half2 t = __floats2half2_rn(a, b);
    return *reinterpret_cast<uint32_t*>(&t);
}

// ---------------- per-batch prep (2 timesteps; pointers batch-local) ----------------
__global__ void k_init(float* __restrict__ deg, int* __restrict__ cnt,
                       float* __restrict__ sig) {
    int i = blockIdx.x * blockDim.x + threadIdx.x;
    if (i < NB) { deg[i] = 1.0f; cnt[i] = 0; sig[i] = 0.0f; }
}

// ei = ei_all + B*2*Ee ; w = w_all + B*Ee
__global__ void k_edge_prep(const int* __restrict__ ei, const float* __restrict__ w,
                            float* __restrict__ deg, int* __restrict__ cnt) {
    int ge = blockIdx.x * blockDim.x + threadIdx.x;
    if (ge < EB) {
        int tt = ge / Ee, e = ge - tt * Ee;
        int c = ei[(size_t)tt * 2 * Ee + Ee + e];
        int lc = tt * Nn + c;
        atomicAdd(&deg[lc], w[ge]);
        atomicAdd(&cnt[lc], 1);
    }
}

__global__ void k_finalize_dinv(float* __restrict__ deg) {
    int i = blockIdx.x * blockDim.x + threadIdx.x;
    if (i < NB) {
        float d = deg[i];
        deg[i] = (d > 0.0f) ? rsqrtf(d) : 0.0f;
    }
}

__global__ void __launch_bounds__(1024)
k_scan1(const int* __restrict__ cnt, int* __restrict__ ptr, int* __restrict__ cur,
        int* __restrict__ bsum) {
    __shared__ int wt[32];
    int tid = threadIdx.x, lane = tid & 31, wid = tid >> 5;
    int i0 = blockIdx.x * 4096 + tid * 4;
    int4 v = make_int4(0, 0, 0, 0);
    if (i0 + 3 < NB) v = *(const int4*)(cnt + i0);
    else {
        if (i0 < NB)     v.x = cnt[i0];
        if (i0 + 1 < NB) v.y = cnt[i0 + 1];
        if (i0 + 2 < NB) v.z = cnt[i0 + 2];
    }
    int tsum = v.x + v.y + v.z + v.w;
    int s = tsum;
#pragma unroll
    for (int off = 1; off < 32; off <<= 1) {
        int t = __shfl_up_sync(0xffffffffu, s, off);
        if (lane >= off) s += t;
    }
    if (lane == 31) wt[wid] = s;
    __syncthreads();
    if (wid == 0) {
        int ws = wt[lane];
#pragma unroll
        for (int off = 1; off < 32; off <<= 1) {
            int t = __shfl_up_sync(0xffffffffu, ws, off);
            if (lane >= off) ws += t;
        }
        wt[lane] = ws;
    }
    __syncthreads();
    int excl = s - tsum + (wid > 0 ? wt[wid - 1] : 0);
    int p = excl;
    if (i0 < NB)     { cur[i0] = p;     ptr[i0 + 1] = p + v.x; } p += v.x;
    if (i0 + 1 < NB) { cur[i0 + 1] = p; ptr[i0 + 2] = p + v.y; } p += v.y;
    if (i0 + 2 < NB) { cur[i0 + 2] = p; ptr[i0 + 3] = p + v.z; } p += v.z;
    if (i0 + 3 < NB) { cur[i0 + 3] = p; ptr[i0 + 4] = p + v.w; }
    if (tid == 1023) bsum[blockIdx.x] = excl + tsum;
}

__global__ void k_scan2(const int* __restrict__ bsum, int* __restrict__ boff,
                        int* __restrict__ ptr) {
    if (threadIdx.x == 0) {
        ptr[0] = 0;
        int run = 0;
        for (int b = 0; b < SCAN_BLKB; b++) { boff[b] = run; run += bsum[b]; }
    }
}

__global__ void __launch_bounds__(1024)
k_scan3(const int* __restrict__ boff, int* __restrict__ ptr, int* __restrict__ cur) {
    int off = boff[blockIdx.x];
    int i0 = blockIdx.x * 4096 + threadIdx.x * 4;
#pragma unroll
    for (int k = 0; k < 4; k++) {
        int i = i0 + k;
        if (i < NB) { cur[i] += off; ptr[i + 1] += off; }
    }
}

__global__ void k_permute(const int* __restrict__ ei, const float* __restrict__ w,
                          const float* __restrict__ dinv, int* __restrict__ cur,
                          int* __restrict__ erow, float* __restrict__ enorm,
                          float* __restrict__ sig) {
    int ge = blockIdx.x * blockDim.x + threadIdx.x;
    if (ge < EB) {
        int tt = ge / Ee, e = ge - tt * Ee;
        const int* base = ei + (size_t)tt * 2 * Ee;
        int r = base[e], c = base[Ee + e];
        int lr = tt * Nn + r, lc = tt * Nn + c;
        float nm = dinv[lr] * w[ge] * dinv[lc];
        int pos = atomicAdd(&cur[lc], 1);
        erow[pos] = r;          // row LOCAL to its timestep
        enorm[pos] = nm;
        atomicAdd(&sig[lc], nm);
    }
}

__global__ void k_sigma_fin(const float* __restrict__ dinv, float* __restrict__ sig) {
    int i = blockIdx.x * blockDim.x + threadIdx.x;
    if (i < NB) {
        float d = dinv[i];
        sig[i] += d * d;
    }
}

__global__ void k_msigma(const int* __restrict__ ptr, const int* __restrict__ erow,
                         const float* __restrict__ enorm, const float* __restrict__ dinv,
                         const float* __restrict__ sig, float* __restrict__ msig) {
    int i = blockIdx.x * blockDim.x + threadIdx.x;
    if (i < NB) {
        int tt = i / Nn;
        float d = dinv[i];
        float s = d * d * sig[i];
        int jb = ptr[i], je = ptr[i + 1];
        const float* sbase = sig + (size_t)tt * Nn;
        for (int j = jb; j < je; j++)
            s = fmaf(enorm[j], sbase[erow[j]], s);
        msig[i] = s;
    }
}

// per-batch gather (2 timesteps)
__global__ void k_gather(const int* __restrict__ ids, const float4* __restrict__ emb,
                         uint2* __restrict__ x) {
    int idx = blockIdx.x * blockDim.x + threadIdx.x;
    if (idx < NB * 64) {
        int i = idx >> 6, q = idx & 63;
        float4 v = emb[(size_t)ids[i] * 64 + q];
        x[idx] = make_uint2(f2h2(v.x, v.y), f2h2(v.z, v.w));
    }
}

// ---------------- weight precompute ----------------
__global__ void __launch_bounds__(256)
k_mm256(const float* __restrict__ A, const float* __restrict__ B, float* __restrict__ C) {
    const int BM = 128, BN = 128, BK = 16, TM = 8, TN = 8;
    __shared__ float As[BK][BM + 4];
    __shared__ float Bs[BK][BN];
    int tid = threadIdx.x;
    int m0 = blockIdx.x * BM, n0 = blockIdx.y * BN;
    int arow = tid >> 2, acol = (tid & 3) << 2;
    int brow = tid >> 5, bcol = (tid & 31) << 2;
    int tr = (tid >> 4) * TM, tc = (tid & 15) * TN;
    float acc[TM][TN] = {};
    for (int k0 = 0; k0 < Dd; k0 += BK) {
#pragma unroll
        for (int i = 0; i < 2; i++) {
            int r = arow + i * 64;
            float4 v = *(const float4*)(A + (size_t)(m0 + r) * Dd + k0 + acol);
            As[acol + 0][r] = v.x; As[acol + 1][r] = v.y;
            As[acol + 2][r] = v.z; As[acol + 3][r] = v.w;
        }
#pragma unroll
        for (int i = 0; i < 2; i++) {
            int r = brow + i * 8;
            *(float4*)&Bs[r][bcol] = *(const float4*)(B + (size_t)(k0 + r) * Dd + n0 + bcol);
        }
        __syncthreads();
#pragma unroll
        for (int kk = 0; kk < BK; kk++) {
            float ar[TM], br[TN];
#pragma unroll
            for (int i = 0; i < TM; i++) ar[i] = As[kk][tr + i];
#pragma unroll
            for (int j = 0; j < TN; j++) br[j] = Bs[kk][tc + j];
#pragma unroll
            for (int i = 0; i < TM; i++)
#pragma unroll
                for (int j = 0; j < TN; j++)
                    acc[i][j] = fmaf(ar[i], br[j], acc[i][j]);
        }
        __syncthreads();
    }
#pragma unroll
    for (int i = 0; i < TM; i++)
#pragma unroll
        for (int j = 0; j < TN; j += 4)
            *(float4*)(C + (size_t)(m0 + tr + i) * Dd + n0 + tc + j) =
                make_float4(acc[i][j], acc[i][j + 1], acc[i][j + 2], acc[i][j + 3]);
}

__global__ void k_vecmat(const float* __restrict__ b, const float* __restrict__ M,
                         float* __restrict__ c) {
    int n = blockIdx.x * 8 + (threadIdx.x >> 5);
    int lane = threadIdx.x & 31;
    if (n >= Dd) return;
    float s = 0.0f;
    for (int a = lane; a < Dd; a += 32)
        s = fmaf(b[a], M[a * Dd + n], s);
#pragma unroll
    for (int off = 16; off > 0; off >>= 1)
        s += __shfl_down_sync(0xffffffffu, s, off);
    if (lane == 0) c[n] = s;
}

__global__ void k_wprep(const float* __restrict__ W, __half* __restrict__ wt) {
    int idx = blockIdx.x * blockDim.x + threadIdx.x;
    if (idx < Dd * Dd) {
        int n = idx >> 8, k = idx & 255;
        wt[idx] = __float2half_rn(W[k * Dd + n]);
    }
}

// ---------------- aggregate: Y = M * X ----------------
__global__ void __launch_bounds__(256)
k_aggregate(const int* __restrict__ ptr, const int* __restrict__ erow,
            const float* __restrict__ enorm, const uint4* __restrict__ src,
            const float* __restrict__ dinv, uint4* __restrict__ dst) {
    int warp = (blockIdx.x * blockDim.x + threadIdx.x) >> 5;
    int lane = threadIdx.x & 31;
    if (warp >= Nn) return;
    int node = warp;

    float s = dinv[node];
    s = s * s;
    float f[8], acc[8];
    h8f(src[(size_t)node * 32 + lane], f);
#pragma unroll
    for (int i = 0; i < 8; i++) acc[i] = s * f[i];

    int jb = ptr[node], je = ptr[node + 1];
    int j = jb;
    for (; j + 1 < je; j += 2) {
        int ra = erow[j], rb = erow[j + 1];
        float na = enorm[j], nb = enorm[j + 1];
        uint4 va = src[(size_t)ra * 32 + lane];
        uint4 vb = src[(size_t)rb * 32 + lane];
        float fa[8], fb[8];
        h8f(va, fa); h8f(vb, fb);
#pragma unroll
        for (int i = 0; i < 8; i++) acc[i] = fmaf(na, fa[i], acc[i]);
#pragma unroll
        for (int i = 0; i < 8; i++) acc[i] = fmaf(nb, fb[i], acc[i]);
    }
    if (j < je) {
        int r = erow[j];
        float nm = enorm[j];
        float fr[8];
        h8f(src[(size_t)r * 32 + lane], fr);
#pragma unroll
        for (int i = 0; i < 8; i++) acc[i] = fmaf(nm, fr[i], acc[i]);
    }

    dst[(size_t)node * 32 + lane] = make_uint4(f2h2(acc[0], acc[1]), f2h2(acc[2], acc[3]),
                                               f2h2(acc[4], acc[5]), f2h2(acc[6], acc[7]));
}

// ---------------- final GEMM + bias epilogue ----------------
__device__ __forceinline__ uint32_t swz(int row, int c) {
    return (uint32_t)(row * 64 + ((c ^ ((row >> 1) & 3)) << 4));
}

#define GEMM_SMEM 32768

__global__ void __launch_bounds__(256)
k_gemm_out(const __half* __restrict__ y, const __half* __restrict__ wtp,
           const float* __restrict__ sig, const float* __restrict__ msig,
           const float* __restrict__ c1, const float* __restrict__ c2,
           const float* __restrict__ b3, float* __restrict__ out) {
    extern __shared__ __align__(128) char sm[];

    const int tid = threadIdx.x;
    const int wid = tid >> 5, lane = tid & 31;
    const int m0 = blockIdx.x * 128, n0 = blockIdx.y * 128;
    const int mw = wid >> 2, nw = wid & 3;

    float acc[4][4][4] = {};

    auto issue = [&](int kc, int stage) {
        char* sbase = sm + stage * 16384;
#pragma unroll
        for (int i = 0; i < 4; i++) {
            int u = tid + i * 256;
            int tile = u >> 9, idx = u & 511;
            int row = idx >> 2, c = idx & 3;
            uint32_t dst = (uint32_t)__cvta_generic_to_shared(
                sbase + tile * 8192 + swz(row, c));
            if (tile == 0) {
                int gm = m0 + row;
                int ok = (gm < Nn);
                const void* src = y + (size_t)(ok ? gm : 0) * Dd + kc * 32 + c * 8;
                int sz = ok ? 16 : 0;
                asm volatile("cp.async.ca.shared.global [%0], [%1], 16, %2;"
                             :: "r"(dst), "l"(src), "r"(sz));
            } else {
                const void* src = wtp + (size_t)(n0 + row) * Dd + kc * 32 + c * 8;
                asm volatile("cp.async.ca.shared.global [%0], [%1], 16;"
                             :: "r"(dst), "l"(src));
            }
        }
        asm volatile("cp.async.commit_group;");
    };

    issue(0, 0);
    for (int it = 0; it < 8; it++) {
        int buf = it & 1;
        if (it + 1 < 8) {
            issue(it + 1, buf ^ 1);
            asm volatile("cp.async.wait_group 1;");
        } else {
            asm volatile("cp.async.wait_group 0;");
        }
        __syncthreads();
        char* pA = sm + buf * 16384;
        char* pB = pA + 8192;

#pragma unroll
        for (int ks = 0; ks < 2; ks++) {
            int ac = ks * 2 + ((lane >> 4) & 1);
            int brow = (lane & 7) + ((lane & 16) ? 8 : 0);
            int bc = ks * 2 + ((lane & 8) ? 1 : 0);
            uint32_t af[4][4];
#pragma unroll
            for (int mt = 0; mt < 4; mt++) {
                int row = mw * 64 + mt * 16 + (lane & 15);
                uint32_t a = (uint32_t)__cvta_generic_to_shared(pA + swz(row, ac));
                asm volatile("ldmatrix.sync.aligned.m8n8.x4.shared.b16 {%0,%1,%2,%3}, [%4];"
                             : "=r"(af[mt][0]), "=r"(af[mt][1]),
                               "=r"(af[mt][2]), "=r"(af[mt][3]) : "r"(a));
            }
            uint32_t bf[4][2];
#pragma unroll
            for (int ntp = 0; ntp < 2; ntp++) {
                int row = nw * 32 + ntp * 16 + brow;
                uint32_t b = (uint32_t)__cvta_generic_to_shared(pB + swz(row, bc));
                uint32_t r0, r1, r2, r3;
                asm volatile("ldmatrix.sync.aligned.m8n8.x4.shared.b16 {%0,%1,%2,%3}, [%4];"
                             : "=r"(r0), "=r"(r1), "=r"(r2), "=r"(r3) : "r"(b));
                bf[ntp * 2][0] = r0; bf[ntp * 2][1] = r1;
                bf[ntp * 2 + 1][0] = r2; bf[ntp * 2 + 1][1] = r3;
            }
#pragma unroll
            for (int mt = 0; mt < 4; mt++)
#pragma unroll
                for (int nt = 0; nt < 4; nt++) {
                    asm volatile(
                        "mma.sync.aligned.m16n8k16.row.col.f32.f16.f16.f32 "
                        "{%0,%1,%2,%3}, {%4,%5,%6,%7}, {%8,%9}, {%0,%1,%2,%3};"
                        : "+f"(acc[mt][nt][0]), "+f"(acc[mt][nt][1]),
                          "+f"(acc[mt][nt][2]), "+f"(acc[mt][nt][3])
                        : "r"(af[mt][0]), "r"(af[mt][1]), "r"(af[mt][2]), "r"(af[mt][3]),
                          "r"(bf[nt][0]), "r"(bf[nt][1]));
                }
        }
        __syncthreads();
    }

#pragma unroll
    for (int mt = 0; mt < 4; mt++) {
        int mm = m0 + mw * 64 + mt * 16 + (lane >> 2);
        float s1a = 0.f, s2a = 0.f, s1b = 0.f, s2b = 0.f;
        if (mm < Nn)     { s1a = msig[mm];     s2a = sig[mm]; }
        if (mm + 8 < Nn) { s1b = msig[mm + 8]; s2b = sig[mm + 8]; }
#pragma unroll
        for (int nt = 0; nt < 4; nt++) {
            int cc = n0 + nw * 32 + nt * 8 + 2 * (lane & 3);
            float e0 = c1[cc], e1 = c1[cc + 1];
            float g0 = c2[cc], g1 = c2[cc + 1];
            float h0 = b3[cc], h1 = b3[cc + 1];
            if (mm < Nn) {
                float o0 = acc[mt][nt][0] + s1a * e0 + s2a * g0 + h0;
                float o1 = acc[mt][nt][1] + s1a * e1 + s2a * g1 + h1;
                *(float2*)(out + (size_t)mm * Dd + cc) = make_float2(o0, o1);
            }
            if (mm + 8 < Nn) {
                float o0 = acc[mt][nt][2] + s1b * e0 + s2b * g0 + h0;
                float o1 = acc[mt][nt][3] + s1b * e1 + s2b * g1 + h1;
                *(float2*)(out + (size_t)(mm + 8) * Dd + cc) = make_float2(o0, o1);
            }
        }
    }
}

// ---------------- launch ----------------
extern "C" void kernel_launch(void* const* d_in, const int* in_sizes, int n_in,
                              void* d_out, int out_size) {
    const int*   ids_all = (const int*)d_in[0];
    const int*   ei_all  = (const int*)d_in[1];
    const float* w_all   = (const float*)d_in[2];
    const float* emb     = (const float*)d_in[3];
    const float* W1 = (const float*)d_in[4];
    const float* b1 = (const float*)d_in[5];
    const float* W2 = (const float*)d_in[6];
    const float* b2 = (const float*)d_in[7];
    const float* W3 = (const float*)d_in[8];
    const float* b3 = (const float*)d_in[9];
    float* out = (float*)d_out;

    void *px, *py, *pT2, *pWp, *pwtp, *pc1, *pc2, *pd, *psg, *pms,
         *pc, *pu, *pp, *pe, *pm, *pbs, *pbo;
    cudaGetSymbolAddress(&px,  g_x);
    cudaGetSymbolAddress(&py,  g_y);
    cudaGetSymbolAddress(&pT2, g_T2);
    cudaGetSymbolAddress(&pWp, g_Wp32);
    cudaGetSymbolAddress(&pwtp, g_wtp);
    cudaGetSymbolAddress(&pc1, g_c1);
    cudaGetSymbolAddress(&pc2, g_c2);
    cudaGetSymbolAddress(&pd,  g_dinv);
    cudaGetSymbolAddress(&psg, g_sig);
    cudaGetSymbolAddress(&pms, g_msig);
    cudaGetSymbolAddress(&pc,  g_cnt);
    cudaGetSymbolAddress(&pu,  g_cur);
    cudaGetSymbolAddress(&pp,  g_ptr);
    cudaGetSymbolAddress(&pe,  g_erow);
    cudaGetSymbolAddress(&pm,  g_enorm);
    cudaGetSymbolAddress(&pbs, g_bsum);
    cudaGetSymbolAddress(&pbo, g_boff);
    __half* x   = (__half*)px;
    __half* y   = (__half*)py;
    float*  T2  = (float*)pT2;
    float*  Wp  = (float*)pWp;
    __half* wtp = (__half*)pwtp;
    float*  c1  = (float*)pc1;
    float*  c2  = (float*)pc2;
    float* dinv = (float*)pd;
    float* sig  = (float*)psg;
    float* msig = (float*)pms;
    int* cnt = (int*)pc;
    int* cur = (int*)pu;
    int* ptr = (int*)pp;
    int* erow = (int*)pe;
    float* enrm = (float*)pm;
    int* bsum = (int*)pbs;
    int* boff = (int*)pbo;

    const int TPB = 256;
    static cudaStream_t st1 = nullptr, st2 = nullptr, st3 = nullptr;
    static cudaEvent_t evStart = nullptr, evA = nullptr, evB = nullptr;
    static cudaEvent_t evAgg0 = nullptr, evAgg2 = nullptr, evAgg3 = nullptr;
    if (!st1) {
        cudaStreamCreateWithFlags(&st1, cudaStreamNonBlocking);
        cudaStreamCreateWithFlags(&st2, cudaStreamNonBlocking);
        cudaStreamCreateWithFlags(&st3, cudaStreamNonBlocking);
        cudaEventCreateWithFlags(&evStart, cudaEventDisableTiming);
        cudaEventCreateWithFlags(&evA, cudaEventDisableTiming);
        cudaEventCreateWithFlags(&evB, cudaEventDisableTiming);
        cudaEventCreateWithFlags(&evAgg0, cudaEventDisableTiming);
        cudaEventCreateWithFlags(&evAgg2, cudaEventDisableTiming);
        cudaEventCreateWithFlags(&evAgg3, cudaEventDisableTiming);
        cudaFuncSetAttribute(k_gemm_out, cudaFuncAttributeMaxDynamicSharedMemorySize,
                             GEMM_SMEM);
    }

    int aggBlocks = (Nn * 32 + TPB - 1) / TPB;
    dim3 ggrid((Nn + 127) / 128, Dd / 128);
    dim3 mmgrid(2, 2);

    cudaEventRecord(evStart, (cudaStream_t)0);
    cudaStreamWaitEvent(st1, evStart, 0);
    cudaStreamWaitEvent(st2, evStart, 0);
    cudaStreamWaitEvent(st3, evStart, 0);

    // ---- per-batch prep on st1 (batch 0 = t0,t1) and st2 (batch 1 = t2,t3) ----
    cudaStream_t bst[2] = {st1, st2};
    for (int bb = 0; bb < 2; bb++) {
        cudaStream_t s = bst[bb];
        const int*   eiB  = ei_all + (size_t)bb * 2 * 2 * Ee;
        const float* wB   = w_all + (size_t)bb * 2 * Ee;
        const int*   idsB = ids_all + (size_t)bb * NB;
        float* dB = dinv + (size_t)bb * NB;
        float* sB = sig  + (size_t)bb * NB;
        float* mB = msig + (size_t)bb * NB;
        int* cntB = cnt + (size_t)bb * NB;
        int* curB = cur + (size_t)bb * NB;
        int* ptrB = ptr + (size_t)bb * (NB + 1);
        int* erB  = erow + (size_t)bb * EB;
        float* enB = enrm + (size_t)bb * EB;
        int* bsB = bsum + bb * 32;
        int* boB = boff + bb * 32;
        __half* xB = x + (size_t)bb * NB * Dd;

        k_init<<<(NB + TPB - 1) / TPB, TPB, 0, s>>>(dB, cntB, sB);
        k_edge_prep<<<(EB + TPB - 1) / TPB, TPB, 0, s>>>(eiB, wB, dB, cntB);
        k_finalize_dinv<<<(NB + TPB - 1) / TPB, TPB, 0, s>>>(dB);
        k_scan1<<<SCAN_BLKB, 1024, 0, s>>>(cntB, ptrB, curB, bsB);
        k_scan2<<<1, 32, 0, s>>>(bsB, boB, ptrB);
        k_scan3<<<SCAN_BLKB, 1024, 0, s>>>(boB, ptrB, curB);
        k_permute<<<(EB + TPB - 1) / TPB, TPB, 0, s>>>(eiB, wB, dB, curB, erB, enB, sB);
        k_sigma_fin<<<(NB + TPB - 1) / TPB, TPB, 0, s>>>(dB, sB);
        k_msigma<<<(NB + TPB - 1) / TPB, TPB, 0, s>>>(ptrB, erB, enB, dB, sB, mB);
        k_gather<<<(NB * 64 + TPB - 1) / TPB, TPB, 0, s>>>(idsB, (const float4*)emb,
                                                           (uint2*)xB);
        cudaEventRecord(bb == 0 ? evA : evB, s);
    }

    // ---- weight chain on default stream (concurrent with batch preps) ----
    k_mm256<<<mmgrid, 256>>>(W2, W3, T2);
    k_mm256<<<mmgrid, 256>>>(W1, T2, Wp);
    k_wprep<<<(Dd * Dd + TPB - 1) / TPB, TPB>>>(Wp, wtp);
    k_vecmat<<<32, 256>>>(b1, T2, c1);
    k_vecmat<<<32, 256>>>(b2, W3, c2);

    // ---- aggregate chains ----
    // helper lambda: 3-hop aggregate for timestep t on stream s
    auto aggChain = [&](int t, cudaStream_t s) {
        int bb = t >> 1, lt = t & 1;
        size_t off = (size_t)t * Nn * Dd;
        __half* xt = x + off;
        __half* yt = y + off;
        const int* ptrT = ptr + (size_t)bb * (NB + 1) + (size_t)lt * Nn;
        const int* erB  = erow + (size_t)bb * EB;
        const float* enB = enrm + (size_t)bb * EB;
        const float* dT = dinv + (size_t)t * Nn;
        k_aggregate<<<aggBlocks, TPB, 0, s>>>(ptrT, erB, enB, (const uint4*)xt, dT,
                                              (uint4*)yt);
        k_aggregate<<<aggBlocks, TPB, 0, s>>>(ptrT, erB, enB, (const uint4*)yt, dT,
                                              (uint4*)xt);
        k_aggregate<<<aggBlocks, TPB, 0, s>>>(ptrT, erB, enB, (const uint4*)xt, dT,
                                              (uint4*)yt);
    };

    // st1: t0 chain (stream-ordered after batch-0 prep)
    aggChain(0, st1);
    cudaEventRecord(evAgg0, st1);
    // st2: t2 chain (stream-ordered after batch-1 prep)
    aggChain(2, st2);
    cudaEventRecord(evAgg2, st2);
    // st3: t3 chain (head-wait on batch-1 prep)
    cudaStreamWaitEvent(st3, evB, 0);
    aggChain(3, st3);
    cudaEventRecord(evAgg3, st3);
    // default: t1 chain (wait batch-0 prep) + all gemms (mid-waits on default only)
    cudaStreamWaitEvent((cudaStream_t)0, evA, 0);
    aggChain(1, (cudaStream_t)0);

    auto gemmOut = [&](int t) {
        size_t off = (size_t)t * Nn * Dd;
        k_gemm_out<<<ggrid, 256, GEMM_SMEM>>>(y + off, wtp,
                                              sig + (size_t)t * Nn,
                                              msig + (size_t)t * Nn,
                                              c1, c2, b3, out + off);
    };
    gemmOut(1);
    cudaStreamWaitEvent((cudaStream_t)0, evAgg0, 0);
    gemmOut(0);
    cudaStreamWaitEvent((cudaStream_t)0, evAgg2, 0);
    gemmOut(2);
    cudaStreamWaitEvent((cudaStream_t)0, evAgg3, 0);
    gemmOut(3);
}